// round 1
// baseline (speedup 1.0000x reference)
#include <cuda_runtime.h>
#include <math.h>

#define NN 100000
#define MM 800000
#define KK 6
#define HH 64
#define NHD 4
#define DHD 16

// ---------------- scratch (device globals; allocation-free) ----------------
__device__ float g_h[NN * KK * HH];      // proj output (tanh)
__device__ float g_agg[NN * KK * HH];    // aggregated h
__device__ float g_h2[NN * KK * HH];     // post-GCN relu
__device__ float g_hmid[NN * HH];        // post-attn LN1 (row k=5 only)
__device__ float g_hfinal[NN * HH];      // post-FF LN2 (row k=5 only)
__device__ float g_dinv[NN];
__device__ int   g_counts[NN];
__device__ int   g_rowstart[NN + 1];
__device__ int   g_cursor[NN];
__device__ int   g_srclist[MM];
__device__ float g_ck[KK * HH];          // k-dependent proj constants

// ---------------- small utility kernels ----------------
__global__ void k_zero_counts() {
    int i = blockIdx.x * blockDim.x + threadIdx.x;
    if (i < NN) g_counts[i] = 0;
}

__global__ void k_count(const int* __restrict__ ei) {
    int e = blockIdx.x * blockDim.x + threadIdx.x;
    if (e < MM) atomicAdd(&g_counts[ei[MM + e]], 1);
}

__global__ void k_dinv() {
    int n = blockIdx.x * blockDim.x + threadIdx.x;
    if (n < NN) g_dinv[n] = rsqrtf((float)g_counts[n] + 1.0f);
}

// single-block exclusive scan over counts -> rowstart, cursor
__global__ void k_scan() {
    __shared__ int sdata[1024];
    __shared__ int carry;
    int t = threadIdx.x;
    if (t == 0) carry = 0;
    __syncthreads();
    for (int base = 0; base < NN; base += 1024) {
        int cbase = carry;
        int i = base + t;
        int v = (i < NN) ? g_counts[i] : 0;
        sdata[t] = v;
        __syncthreads();
        for (int off = 1; off < 1024; off <<= 1) {
            int tv = (t >= off) ? sdata[t - off] : 0;
            __syncthreads();
            sdata[t] += tv;
            __syncthreads();
        }
        if (i < NN) {
            int excl = cbase + sdata[t] - v;
            g_rowstart[i] = excl;
            g_cursor[i]   = excl;
        }
        __syncthreads();
        if (t == 0) carry = cbase + sdata[1023];
        __syncthreads();
    }
    if (t == 0) g_rowstart[NN] = carry;
}

__global__ void k_fill(const int* __restrict__ ei) {
    int e = blockIdx.x * blockDim.x + threadIdx.x;
    if (e < MM) {
        int d = ei[MM + e];
        int p = atomicAdd(&g_cursor[d], 1);
        g_srclist[p] = ei[e];
    }
}

// c[k][c] = b_proj[c] + sum_j u[j]*Wp[12+j][c] + sum_j u_seq[k][j]*Wp[23+j][c]
__global__ void k_ck(const float* __restrict__ W_proj, const float* __restrict__ b_proj,
                     const float* __restrict__ u, const float* __restrict__ u_seq) {
    int c = threadIdx.x;
    if (c >= HH) return;
    float base = b_proj[c];
#pragma unroll
    for (int j = 0; j < 11; j++) base += u[j] * W_proj[(12 + j) * HH + c];
    for (int k = 0; k < KK; k++) {
        float val = base;
#pragma unroll
        for (int j = 0; j < 5; j++) val += u_seq[k * 5 + j] * W_proj[(23 + j) * HH + c];
        g_ck[k * HH + c] = val;
    }
}

// ---------------- projection: h[n,k,c] = tanh(dot12(x[n], Wp) + ck[k,c]) ----------------
__global__ __launch_bounds__(256) void k_proj(const float* __restrict__ x,
                                              const float* __restrict__ W_proj) {
    __shared__ float Wp12[12 * HH];
    __shared__ float cks[KK * HH];
    int t = threadIdx.x;
    for (int i = t; i < 12 * HH; i += 256) Wp12[i] = W_proj[i];
    for (int i = t; i < KK * HH; i += 256) cks[i] = g_ck[i];
    __syncthreads();
    int g = t >> 6, c = t & 63;
    int n = blockIdx.x * 4 + g;
    float s = 0.f;
#pragma unroll
    for (int j = 0; j < 12; j++) s += __ldg(&x[n * 12 + j]) * Wp12[j * HH + c];
    int base = n * (KK * HH) + c;
#pragma unroll
    for (int k = 0; k < KK; k++) g_h[base + k * HH] = tanhf(s + cks[k * HH + c]);
}

// ---------------- aggregation: agg[n,k,:] = sum_in h[src,k,:]*w + h[n,k,:]*self ----------
__global__ __launch_bounds__(192) void k_aggregate() {
    int n = blockIdx.x;
    int w = threadIdx.x >> 5;   // k slice 0..5
    int l = threadIdx.x & 31;
    float dn = g_dinv[n];
    float selfw = dn * dn;
    int s0 = g_rowstart[n], s1 = g_rowstart[n + 1];
    const float2* hself = (const float2*)&g_h[n * (KK * HH) + w * HH];
    float2 hv = hself[l];
    float accx = hv.x * selfw, accy = hv.y * selfw;
    for (int i = s0; i < s1; i++) {
        int sn = g_srclist[i];
        float wg = g_dinv[sn] * dn;
        float2 v = *(const float2*)&g_h[sn * (KK * HH) + w * HH + 2 * l];
        accx += v.x * wg;
        accy += v.y * wg;
    }
    float2* outp = (float2*)&g_agg[n * (KK * HH) + w * HH];
    outp[l] = make_float2(accx, accy);
}

// ---------------- GCN: h2 = relu(agg @ W_gcn + b_gcn) ----------------
__global__ __launch_bounds__(256) void k_gcn(const float* __restrict__ W_gcn,
                                             const float* __restrict__ b_gcn) {
    __shared__ float Wg[HH * HH];
    __shared__ float bg[HH];
    __shared__ float rows[8][HH];
    int t = threadIdx.x;
    for (int i = t; i < HH * HH; i += 256) Wg[i] = W_gcn[i];
    if (t < HH) bg[t] = b_gcn[t];
    __syncthreads();
    int w = t >> 5, l = t & 31, c = 2 * l;
    for (int row = blockIdx.x * 8 + w; row < NN * KK; row += gridDim.x * 8) {
        float2 rv = *(const float2*)&g_agg[row * HH + c];
        rows[w][c] = rv.x; rows[w][c + 1] = rv.y;
        __syncwarp();
        float ax = bg[c], ay = bg[c + 1];
#pragma unroll
        for (int j = 0; j < HH; j++) {
            float r = rows[w][j];
            float2 wv = *(const float2*)&Wg[j * HH + c];
            ax += r * wv.x;
            ay += r * wv.y;
        }
        __syncwarp();
        ax = fmaxf(ax, 0.f); ay = fmaxf(ay, 0.f);
        *(float2*)&g_h2[row * HH + c] = make_float2(ax, ay);
    }
}

// ---------------- attention (q-row 5 only) + LN1 ----------------
struct SAttn {
    float Wq[HH * HH], Wk[HH * HH], Wv[HH * HH], Wo[HH * HH];
    float bq[HH], bk[HH], bv[HH], bo[HH], g1[HH], be1[HH];
    float hrow[KK * HH];
    float qs[HH], ks[KK * HH], vs[KK * HH];
    float sc[NHD * KK], aw[NHD * KK];
    float aos[HH], ys[HH];
    float mv[2];
};

__device__ __forceinline__ void attn_row(SAttn& s, int r, int l) {
    const float* W; const float* b; float* out; int inrow;
    if (r == 0)      { W = s.Wq; b = s.bq; out = s.qs;                inrow = KK - 1; }
    else if (r <= 6) { W = s.Wk; b = s.bk; out = &s.ks[(r - 1) * HH]; inrow = r - 1; }
    else             { W = s.Wv; b = s.bv; out = &s.vs[(r - 7) * HH]; inrow = r - 7; }
    int c = 2 * l;
    float ax = b[c], ay = b[c + 1];
    const float* hr = &s.hrow[inrow * HH];
#pragma unroll
    for (int j = 0; j < HH; j++) {
        float rv = hr[j];
        float2 wv = *(const float2*)&W[j * HH + c];
        ax += rv * wv.x;
        ay += rv * wv.y;
    }
    out[c] = ax; out[c + 1] = ay;
}

__global__ __launch_bounds__(256) void k_attn(
    const float* __restrict__ Wq, const float* __restrict__ bq,
    const float* __restrict__ Wk, const float* __restrict__ bk,
    const float* __restrict__ Wv, const float* __restrict__ bv,
    const float* __restrict__ Wo, const float* __restrict__ bo,
    const float* __restrict__ ln1g, const float* __restrict__ ln1b) {
    extern __shared__ char smem_raw[];
    SAttn& s = *reinterpret_cast<SAttn*>(smem_raw);
    int t = threadIdx.x, w = t >> 5, l = t & 31;
    for (int i = t; i < HH * HH; i += 256) {
        s.Wq[i] = Wq[i]; s.Wk[i] = Wk[i]; s.Wv[i] = Wv[i]; s.Wo[i] = Wo[i];
    }
    if (t < HH) {
        s.bq[t] = bq[t]; s.bk[t] = bk[t]; s.bv[t] = bv[t]; s.bo[t] = bo[t];
        s.g1[t] = ln1g[t]; s.be1[t] = ln1b[t];
    }
    for (int n = blockIdx.x; n < NN; n += gridDim.x) {
        __syncthreads();
        for (int i = t; i < KK * HH; i += 256) s.hrow[i] = g_h2[n * (KK * HH) + i];
        __syncthreads();
        // qkv: 13 rows (q row5, k all, v all)
        attn_row(s, w, l);
        if (w < 5) attn_row(s, w + 8, l);
        __syncthreads();
        // scores
        if (t < NHD * KK) {
            int hh = t / KK, kk = t % KK;
            float sv = 0.f;
#pragma unroll
            for (int d = 0; d < DHD; d++) sv += s.qs[hh * DHD + d] * s.ks[kk * HH + hh * DHD + d];
            s.sc[t] = sv * 0.25f;
        }
        __syncthreads();
        if (t < NHD) {
            float mx = -1e30f;
            for (int kk = 0; kk < KK; kk++) mx = fmaxf(mx, s.sc[t * KK + kk]);
            float sum = 0.f, ex[KK];
            for (int kk = 0; kk < KK; kk++) { ex[kk] = expf(s.sc[t * KK + kk] - mx); sum += ex[kk]; }
            float inv = 1.0f / sum;
            for (int kk = 0; kk < KK; kk++) s.aw[t * KK + kk] = ex[kk] * inv;
        }
        __syncthreads();
        if (t < HH) {
            int hh = t >> 4;
            float a = 0.f;
#pragma unroll
            for (int kk = 0; kk < KK; kk++) a += s.aw[hh * KK + kk] * s.vs[kk * HH + t];
            s.aos[t] = a;
        }
        __syncthreads();
        if (t < HH) {
            float o = s.bo[t];
#pragma unroll
            for (int j = 0; j < HH; j++) o += s.aos[j] * s.Wo[j * HH + t];
            s.ys[t] = s.hrow[(KK - 1) * HH + t] + o;
        }
        __syncthreads();
        if (t < 32) {
            float a = s.ys[t], b = s.ys[t + 32];
            float s1 = a + b, s2 = a * a + b * b;
            for (int off = 16; off > 0; off >>= 1) {
                s1 += __shfl_down_sync(0xffffffffu, s1, off);
                s2 += __shfl_down_sync(0xffffffffu, s2, off);
            }
            if (t == 0) {
                float m = s1 * (1.0f / HH);
                float var = s2 * (1.0f / HH) - m * m;
                s.mv[0] = m; s.mv[1] = rsqrtf(var + 1e-5f);
            }
        }
        __syncthreads();
        if (t < HH)
            g_hmid[n * HH + t] = (s.ys[t] - s.mv[0]) * s.mv[1] * s.g1[t] + s.be1[t];
    }
}

// ---------------- FF + LN2 (row 5 only) ----------------
struct SFF {
    float W1[HH * 2 * HH], W2[2 * HH * HH];
    float bb1[2 * HH], bb2[HH], g2[HH], be2[HH];
    float hm[HH], z1[2 * HH], ys[HH];
    float mv[2];
};

__global__ __launch_bounds__(256) void k_ff(
    const float* __restrict__ W_ff1, const float* __restrict__ b_ff1,
    const float* __restrict__ W_ff2, const float* __restrict__ b_ff2,
    const float* __restrict__ ln2g, const float* __restrict__ ln2b) {
    extern __shared__ char smem_raw[];
    SFF& s = *reinterpret_cast<SFF*>(smem_raw);
    int t = threadIdx.x;
    for (int i = t; i < HH * 2 * HH; i += 256) { s.W1[i] = W_ff1[i]; s.W2[i] = W_ff2[i]; }
    if (t < 2 * HH) s.bb1[t] = b_ff1[t];
    if (t < HH) { s.bb2[t] = b_ff2[t]; s.g2[t] = ln2g[t]; s.be2[t] = ln2b[t]; }
    for (int n = blockIdx.x; n < NN; n += gridDim.x) {
        __syncthreads();
        if (t < HH) s.hm[t] = g_hmid[n * HH + t];
        __syncthreads();
        if (t < 2 * HH) {
            float acc = s.bb1[t];
#pragma unroll
            for (int j = 0; j < HH; j++) acc += s.hm[j] * s.W1[j * 2 * HH + t];
            s.z1[t] = fmaxf(acc, 0.f);
        }
        __syncthreads();
        if (t < HH) {
            float acc = s.bb2[t];
#pragma unroll
            for (int j = 0; j < 2 * HH; j++) acc += s.z1[j] * s.W2[j * HH + t];
            s.ys[t] = s.hm[t] + acc;
        }
        __syncthreads();
        if (t < 32) {
            float a = s.ys[t], b = s.ys[t + 32];
            float s1 = a + b, s2 = a * a + b * b;
            for (int off = 16; off > 0; off >>= 1) {
                s1 += __shfl_down_sync(0xffffffffu, s1, off);
                s2 += __shfl_down_sync(0xffffffffu, s2, off);
            }
            if (t == 0) {
                float m = s1 * (1.0f / HH);
                float var = s2 * (1.0f / HH) - m * m;
                s.mv[0] = m; s.mv[1] = rsqrtf(var + 1e-5f);
            }
        }
        __syncthreads();
        if (t < HH)
            g_hfinal[n * HH + t] = (s.ys[t] - s.mv[0]) * s.mv[1] * s.g2[t] + s.be2[t];
    }
}

// ---------------- edge decoder ----------------
#define EIN 137
struct SDec {
    float W1[EIN * HH];       // 137 x 64
    float W2[HH * 32];        // 64 x 32
    float W3[32];
    float b1[HH], b2[32];
    float b3;
    float ein[8][144];
    float z1[8][HH];
};

__global__ __launch_bounds__(256) void k_dec(
    const int* __restrict__ ei,
    const float* __restrict__ edge_attr, const float* __restrict__ edge_seq,
    const float* __restrict__ Wd1, const float* __restrict__ bd1,
    const float* __restrict__ Wd2, const float* __restrict__ bd2,
    const float* __restrict__ Wd3, const float* __restrict__ bd3,
    float* __restrict__ out) {
    extern __shared__ char smem_raw[];
    SDec& s = *reinterpret_cast<SDec*>(smem_raw);
    int t = threadIdx.x, w = t >> 5, l = t & 31;
    for (int i = t; i < EIN * HH; i += 256) s.W1[i] = Wd1[i];
    for (int i = t; i < HH * 32; i += 256) s.W2[i] = Wd2[i];
    if (t < 32) s.W3[t] = Wd3[t];
    if (t < HH) s.b1[t] = bd1[t];
    if (t < 32) s.b2[t] = bd2[t];
    if (t == 0) s.b3 = bd3[0];
    __syncthreads();
    float* ein = s.ein[w];
    float* z1 = s.z1[w];
    for (int e = blockIdx.x * 8 + w; e < MM; e += gridDim.x * 8) {
        int src = ei[e], dst = ei[MM + e];
        ein[l]      = g_hfinal[src * HH + l];
        ein[l + 32] = g_hfinal[src * HH + 32 + l];
        ein[l + 64] = g_hfinal[dst * HH + l];
        ein[l + 96] = g_hfinal[dst * HH + 32 + l];
        if (l < 5) ein[128 + l] = edge_attr[e * 5 + l];
        else if (l < 9) ein[133 + (l - 5)] = edge_seq[e * (KK * 4) + (KK - 1) * 4 + (l - 5)];
        __syncwarp();
        int c = 2 * l;
        float ax = s.b1[c], ay = s.b1[c + 1];
#pragma unroll
        for (int j = 0; j < EIN; j++) {
            float rv = ein[j];
            float2 wv = *(const float2*)&s.W1[j * HH + c];
            ax += rv * wv.x;
            ay += rv * wv.y;
        }
        z1[c] = fmaxf(ax, 0.f);
        z1[c + 1] = fmaxf(ay, 0.f);
        __syncwarp();
        float a2 = s.b2[l];
#pragma unroll
        for (int j = 0; j < HH; j++) a2 += z1[j] * s.W2[j * 32 + l];
        a2 = fmaxf(a2, 0.f);
        float p = a2 * s.W3[l];
        for (int off = 16; off > 0; off >>= 1) p += __shfl_down_sync(0xffffffffu, p, off);
        if (l == 0) out[e] = p + s.b3;
        __syncwarp();
    }
}

// ---------------- launch ----------------
extern "C" void kernel_launch(void* const* d_in, const int* in_sizes, int n_in,
                              void* d_out, int out_size) {
    const float* x        = (const float*)d_in[0];
    const int*   ei       = (const int*)  d_in[1];
    const float* eattr    = (const float*)d_in[2];
    const float* u        = (const float*)d_in[3];
    const float* eseq     = (const float*)d_in[4];
    const float* useq     = (const float*)d_in[5];
    const float* W_proj   = (const float*)d_in[6];
    const float* b_proj   = (const float*)d_in[7];
    const float* W_gcn    = (const float*)d_in[8];
    const float* b_gcn    = (const float*)d_in[9];
    const float* Wq       = (const float*)d_in[10];
    const float* bq       = (const float*)d_in[11];
    const float* Wk       = (const float*)d_in[12];
    const float* bk       = (const float*)d_in[13];
    const float* Wv       = (const float*)d_in[14];
    const float* bv       = (const float*)d_in[15];
    const float* Wo       = (const float*)d_in[16];
    const float* bo       = (const float*)d_in[17];
    const float* ln1g     = (const float*)d_in[18];
    const float* ln1b     = (const float*)d_in[19];
    const float* W_ff1    = (const float*)d_in[20];
    const float* b_ff1    = (const float*)d_in[21];
    const float* W_ff2    = (const float*)d_in[22];
    const float* b_ff2    = (const float*)d_in[23];
    const float* ln2g     = (const float*)d_in[24];
    const float* ln2b     = (const float*)d_in[25];
    const float* Wd1      = (const float*)d_in[26];
    const float* bd1      = (const float*)d_in[27];
    const float* Wd2      = (const float*)d_in[28];
    const float* bd2      = (const float*)d_in[29];
    const float* Wd3      = (const float*)d_in[30];
    const float* bd3      = (const float*)d_in[31];
    float* out = (float*)d_out;

    cudaFuncSetAttribute(k_attn, cudaFuncAttributeMaxDynamicSharedMemorySize, (int)sizeof(SAttn));
    cudaFuncSetAttribute(k_ff,   cudaFuncAttributeMaxDynamicSharedMemorySize, (int)sizeof(SFF));
    cudaFuncSetAttribute(k_dec,  cudaFuncAttributeMaxDynamicSharedMemorySize, (int)sizeof(SDec));

    k_zero_counts<<<(NN + 255) / 256, 256>>>();
    k_count<<<(MM + 255) / 256, 256>>>(ei);
    k_dinv<<<(NN + 255) / 256, 256>>>();
    k_scan<<<1, 1024>>>();
    k_fill<<<(MM + 255) / 256, 256>>>(ei);
    k_ck<<<1, 64>>>(W_proj, b_proj, u, useq);
    k_proj<<<NN / 4, 256>>>(x, W_proj);
    k_aggregate<<<NN, 192>>>();
    k_gcn<<<1184, 256>>>(W_gcn, b_gcn);
    k_attn<<<1332, 256, sizeof(SAttn)>>>(Wq, bq, Wk, bk, Wv, bv, Wo, bo, ln1g, ln1b);
    k_ff<<<1184, 256, sizeof(SFF)>>>(W_ff1, b_ff1, W_ff2, b_ff2, ln2g, ln2b);
    k_dec<<<2048, 256, sizeof(SDec)>>>(ei, eattr, eseq, Wd1, bd1, Wd2, bd2, Wd3, bd3, out);
}

// round 2
// speedup vs baseline: 1.2608x; 1.2608x over previous
#include <cuda_runtime.h>
#include <math.h>

#define NN 100000
#define MM 800000
#define KK 6
#define HH 64
#define NHD 4
#define DHD 16

// ---------------- scratch (device globals; allocation-free) ----------------
__device__ float g_h[NN * KK * HH];      // proj output (tanh)
__device__ float g_agg[NN * KK * HH];    // aggregated h
__device__ float g_h2[NN * KK * HH];     // post-GCN relu
__device__ float g_hmid[NN * HH];        // post-attn LN1 (row k=5 only)
__device__ float g_hfinal[NN * HH];      // post-FF LN2 (row k=5 only)
__device__ float g_pa[NN * HH];          // h_final @ Wd1[0:64]
__device__ float g_pb[NN * HH];          // h_final @ Wd1[64:128] + b1
__device__ float g_dinv[NN];
__device__ int   g_counts[NN];
__device__ int   g_rowstart[NN + 1];
__device__ int   g_cursor[NN];
__device__ int   g_srclist[MM];
__device__ float g_ck[KK * HH];          // k-dependent proj constants

// ---------------- small utility kernels ----------------
__global__ void k_zero_counts() {
    int i = blockIdx.x * blockDim.x + threadIdx.x;
    if (i < NN) g_counts[i] = 0;
}

__global__ void k_count(const int* __restrict__ ei) {
    int e = blockIdx.x * blockDim.x + threadIdx.x;
    if (e < MM) atomicAdd(&g_counts[ei[MM + e]], 1);
}

__global__ void k_dinv() {
    int n = blockIdx.x * blockDim.x + threadIdx.x;
    if (n < NN) g_dinv[n] = rsqrtf((float)g_counts[n] + 1.0f);
}

// single-block scan: thread-serial chunks + warp-shuffle block scan of partials
__global__ __launch_bounds__(1024) void k_scan() {
    __shared__ int warpsums[32];
    const int CH = (NN + 1023) / 1024;   // 98
    int t = threadIdx.x;
    int lane = t & 31, w = t >> 5;
    int beg = t * CH;
    int end = min(beg + CH, NN);
    int local = 0;
    for (int i = beg; i < end; i++) local += g_counts[i];
    // inclusive warp scan of per-thread sums
    int v = local;
#pragma unroll
    for (int off = 1; off < 32; off <<= 1) {
        int x = __shfl_up_sync(0xffffffffu, v, off);
        if (lane >= off) v += x;
    }
    if (lane == 31) warpsums[w] = v;
    __syncthreads();
    if (w == 0) {
        int s = warpsums[lane];
#pragma unroll
        for (int off = 1; off < 32; off <<= 1) {
            int x = __shfl_up_sync(0xffffffffu, s, off);
            if (lane >= off) s += x;
        }
        warpsums[lane] = s;
    }
    __syncthreads();
    int excl = v - local + (w > 0 ? warpsums[w - 1] : 0);
    int run = excl;
    for (int i = beg; i < end; i++) {
        g_rowstart[i] = run;
        g_cursor[i]   = run;
        run += g_counts[i];
    }
    if (t == 1023) g_rowstart[NN] = run;
}

__global__ void k_fill(const int* __restrict__ ei) {
    int e = blockIdx.x * blockDim.x + threadIdx.x;
    if (e < MM) {
        int d = ei[MM + e];
        int p = atomicAdd(&g_cursor[d], 1);
        g_srclist[p] = ei[e];
    }
}

// c[k][c] = b_proj[c] + sum_j u[j]*Wp[12+j][c] + sum_j u_seq[k][j]*Wp[23+j][c]
__global__ void k_ck(const float* __restrict__ W_proj, const float* __restrict__ b_proj,
                     const float* __restrict__ u, const float* __restrict__ u_seq) {
    int c = threadIdx.x;
    if (c >= HH) return;
    float base = b_proj[c];
#pragma unroll
    for (int j = 0; j < 11; j++) base += u[j] * W_proj[(12 + j) * HH + c];
    for (int k = 0; k < KK; k++) {
        float val = base;
#pragma unroll
        for (int j = 0; j < 5; j++) val += u_seq[k * 5 + j] * W_proj[(23 + j) * HH + c];
        g_ck[k * HH + c] = val;
    }
}

// ---------------- projection: h[n,k,c] = tanh(dot12(x[n], Wp) + ck[k,c]) ----------------
__global__ __launch_bounds__(256) void k_proj(const float* __restrict__ x,
                                              const float* __restrict__ W_proj) {
    __shared__ float Wp12[12 * HH];
    __shared__ float cks[KK * HH];
    int t = threadIdx.x;
    for (int i = t; i < 12 * HH; i += 256) Wp12[i] = W_proj[i];
    for (int i = t; i < KK * HH; i += 256) cks[i] = g_ck[i];
    __syncthreads();
    int g = t >> 6, c = t & 63;
    int n = blockIdx.x * 4 + g;
    float s = 0.f;
#pragma unroll
    for (int j = 0; j < 12; j++) s += __ldg(&x[n * 12 + j]) * Wp12[j * HH + c];
    int base = n * (KK * HH) + c;
#pragma unroll
    for (int k = 0; k < KK; k++) g_h[base + k * HH] = tanhf(s + cks[k * HH + c]);
}

// ---------------- aggregation: agg[n,k,:] = sum_in h[src,k,:]*w + h[n,k,:]*self ----------
__global__ __launch_bounds__(192) void k_aggregate() {
    int n = blockIdx.x;
    int w = threadIdx.x >> 5;   // k slice 0..5
    int l = threadIdx.x & 31;
    float dn = g_dinv[n];
    float selfw = dn * dn;
    int s0 = g_rowstart[n], s1 = g_rowstart[n + 1];
    const float2* hself = (const float2*)&g_h[n * (KK * HH) + w * HH];
    float2 hv = hself[l];
    float accx = hv.x * selfw, accy = hv.y * selfw;
    for (int i = s0; i < s1; i++) {
        int sn = g_srclist[i];
        float wg = g_dinv[sn] * dn;
        float2 v = *(const float2*)&g_h[sn * (KK * HH) + w * HH + 2 * l];
        accx += v.x * wg;
        accy += v.y * wg;
    }
    float2* outp = (float2*)&g_agg[n * (KK * HH) + w * HH];
    outp[l] = make_float2(accx, accy);
}

// ---------------- GCN: h2 = relu(agg @ W_gcn + b_gcn) ----------------
__global__ __launch_bounds__(256) void k_gcn(const float* __restrict__ W_gcn,
                                             const float* __restrict__ b_gcn) {
    __shared__ float Wg[HH * HH];
    __shared__ float bg[HH];
    __shared__ float rows[8][HH];
    int t = threadIdx.x;
    for (int i = t; i < HH * HH; i += 256) Wg[i] = W_gcn[i];
    if (t < HH) bg[t] = b_gcn[t];
    __syncthreads();
    int w = t >> 5, l = t & 31, c = 2 * l;
    for (int row = blockIdx.x * 8 + w; row < NN * KK; row += gridDim.x * 8) {
        float2 rv = *(const float2*)&g_agg[row * HH + c];
        rows[w][c] = rv.x; rows[w][c + 1] = rv.y;
        __syncwarp();
        float ax = bg[c], ay = bg[c + 1];
#pragma unroll
        for (int j = 0; j < HH; j++) {
            float r = rows[w][j];
            float2 wv = *(const float2*)&Wg[j * HH + c];
            ax += r * wv.x;
            ay += r * wv.y;
        }
        __syncwarp();
        ax = fmaxf(ax, 0.f); ay = fmaxf(ay, 0.f);
        *(float2*)&g_h2[row * HH + c] = make_float2(ax, ay);
    }
}

// ---------------- attention (q-row 5 only) + LN1 ----------------
struct SAttn {
    float Wq[HH * HH], Wk[HH * HH], Wv[HH * HH], Wo[HH * HH];
    float bq[HH], bk[HH], bv[HH], bo[HH], g1[HH], be1[HH];
    float hrow[KK * HH];
    float qs[HH], ks[KK * HH], vs[KK * HH];
    float sc[NHD * KK], aw[NHD * KK];
    float aos[HH], ys[HH];
    float mv[2];
};

__device__ __forceinline__ void attn_row(SAttn& s, int r, int l) {
    const float* W; const float* b; float* out; int inrow;
    if (r == 0)      { W = s.Wq; b = s.bq; out = s.qs;                inrow = KK - 1; }
    else if (r <= 6) { W = s.Wk; b = s.bk; out = &s.ks[(r - 1) * HH]; inrow = r - 1; }
    else             { W = s.Wv; b = s.bv; out = &s.vs[(r - 7) * HH]; inrow = r - 7; }
    int c = 2 * l;
    float ax = b[c], ay = b[c + 1];
    const float* hr = &s.hrow[inrow * HH];
#pragma unroll
    for (int j = 0; j < HH; j++) {
        float rv = hr[j];
        float2 wv = *(const float2*)&W[j * HH + c];
        ax += rv * wv.x;
        ay += rv * wv.y;
    }
    out[c] = ax; out[c + 1] = ay;
}

__global__ __launch_bounds__(256) void k_attn(
    const float* __restrict__ Wq, const float* __restrict__ bq,
    const float* __restrict__ Wk, const float* __restrict__ bk,
    const float* __restrict__ Wv, const float* __restrict__ bv,
    const float* __restrict__ Wo, const float* __restrict__ bo,
    const float* __restrict__ ln1g, const float* __restrict__ ln1b) {
    extern __shared__ char smem_raw[];
    SAttn& s = *reinterpret_cast<SAttn*>(smem_raw);
    int t = threadIdx.x, w = t >> 5, l = t & 31;
    for (int i = t; i < HH * HH; i += 256) {
        s.Wq[i] = Wq[i]; s.Wk[i] = Wk[i]; s.Wv[i] = Wv[i]; s.Wo[i] = Wo[i];
    }
    if (t < HH) {
        s.bq[t] = bq[t]; s.bk[t] = bk[t]; s.bv[t] = bv[t]; s.bo[t] = bo[t];
        s.g1[t] = ln1g[t]; s.be1[t] = ln1b[t];
    }
    for (int n = blockIdx.x; n < NN; n += gridDim.x) {
        __syncthreads();
        for (int i = t; i < KK * HH; i += 256) s.hrow[i] = g_h2[n * (KK * HH) + i];
        __syncthreads();
        // qkv: 13 rows (q row5, k all, v all)
        attn_row(s, w, l);
        if (w < 5) attn_row(s, w + 8, l);
        __syncthreads();
        // scores
        if (t < NHD * KK) {
            int hh = t / KK, kk = t % KK;
            float sv = 0.f;
#pragma unroll
            for (int d = 0; d < DHD; d++) sv += s.qs[hh * DHD + d] * s.ks[kk * HH + hh * DHD + d];
            s.sc[t] = sv * 0.25f;
        }
        __syncthreads();
        if (t < NHD) {
            float mx = -1e30f;
            for (int kk = 0; kk < KK; kk++) mx = fmaxf(mx, s.sc[t * KK + kk]);
            float sum = 0.f, ex[KK];
            for (int kk = 0; kk < KK; kk++) { ex[kk] = expf(s.sc[t * KK + kk] - mx); sum += ex[kk]; }
            float inv = 1.0f / sum;
            for (int kk = 0; kk < KK; kk++) s.aw[t * KK + kk] = ex[kk] * inv;
        }
        __syncthreads();
        if (t < HH) {
            int hh = t >> 4;
            float a = 0.f;
#pragma unroll
            for (int kk = 0; kk < KK; kk++) a += s.aw[hh * KK + kk] * s.vs[kk * HH + t];
            s.aos[t] = a;
        }
        __syncthreads();
        if (t < HH) {
            float o = s.bo[t];
#pragma unroll
            for (int j = 0; j < HH; j++) o += s.aos[j] * s.Wo[j * HH + t];
            s.ys[t] = s.hrow[(KK - 1) * HH + t] + o;
        }
        __syncthreads();
        if (t < 32) {
            float a = s.ys[t], b = s.ys[t + 32];
            float s1 = a + b, s2 = a * a + b * b;
            for (int off = 16; off > 0; off >>= 1) {
                s1 += __shfl_down_sync(0xffffffffu, s1, off);
                s2 += __shfl_down_sync(0xffffffffu, s2, off);
            }
            if (t == 0) {
                float m = s1 * (1.0f / HH);
                float var = s2 * (1.0f / HH) - m * m;
                s.mv[0] = m; s.mv[1] = rsqrtf(var + 1e-5f);
            }
        }
        __syncthreads();
        if (t < HH)
            g_hmid[n * HH + t] = (s.ys[t] - s.mv[0]) * s.mv[1] * s.g1[t] + s.be1[t];
    }
}

// ---------------- FF + LN2 (row 5 only) ----------------
struct SFF {
    float W1[HH * 2 * HH], W2[2 * HH * HH];
    float bb1[2 * HH], bb2[HH], g2[HH], be2[HH];
    float hm[HH], z1[2 * HH], ys[HH];
    float mv[2];
};

__global__ __launch_bounds__(256) void k_ff(
    const float* __restrict__ W_ff1, const float* __restrict__ b_ff1,
    const float* __restrict__ W_ff2, const float* __restrict__ b_ff2,
    const float* __restrict__ ln2g, const float* __restrict__ ln2b) {
    extern __shared__ char smem_raw[];
    SFF& s = *reinterpret_cast<SFF*>(smem_raw);
    int t = threadIdx.x;
    for (int i = t; i < HH * 2 * HH; i += 256) { s.W1[i] = W_ff1[i]; s.W2[i] = W_ff2[i]; }
    if (t < 2 * HH) s.bb1[t] = b_ff1[t];
    if (t < HH) { s.bb2[t] = b_ff2[t]; s.g2[t] = ln2g[t]; s.be2[t] = ln2b[t]; }
    for (int n = blockIdx.x; n < NN; n += gridDim.x) {
        __syncthreads();
        if (t < HH) s.hm[t] = g_hmid[n * HH + t];
        __syncthreads();
        if (t < 2 * HH) {
            float acc = s.bb1[t];
#pragma unroll
            for (int j = 0; j < HH; j++) acc += s.hm[j] * s.W1[j * 2 * HH + t];
            s.z1[t] = fmaxf(acc, 0.f);
        }
        __syncthreads();
        if (t < HH) {
            float acc = s.bb2[t];
#pragma unroll
            for (int j = 0; j < 2 * HH; j++) acc += s.z1[j] * s.W2[j * HH + t];
            s.ys[t] = s.hm[t] + acc;
        }
        __syncthreads();
        if (t < 32) {
            float a = s.ys[t], b = s.ys[t + 32];
            float s1 = a + b, s2 = a * a + b * b;
            for (int off = 16; off > 0; off >>= 1) {
                s1 += __shfl_down_sync(0xffffffffu, s1, off);
                s2 += __shfl_down_sync(0xffffffffu, s2, off);
            }
            if (t == 0) {
                float m = s1 * (1.0f / HH);
                float var = s2 * (1.0f / HH) - m * m;
                s.mv[0] = m; s.mv[1] = rsqrtf(var + 1e-5f);
            }
        }
        __syncthreads();
        if (t < HH)
            g_hfinal[n * HH + t] = (s.ys[t] - s.mv[0]) * s.mv[1] * s.g2[t] + s.be2[t];
    }
}

// ---------------- decoder precompute: pa = h@W1a, pb = h@W1b + b1 ----------------
__global__ __launch_bounds__(256) void k_predec(const float* __restrict__ Wd1,
                                                const float* __restrict__ bd1) {
    __shared__ float Wa[HH * HH];   // rows 0..63 of Wd1
    __shared__ float Wb[HH * HH];   // rows 64..127
    __shared__ float b1s[HH];
    __shared__ float rows[8][HH];
    int t = threadIdx.x;
    for (int i = t; i < HH * HH; i += 256) { Wa[i] = Wd1[i]; Wb[i] = Wd1[HH * HH + i]; }
    if (t < HH) b1s[t] = bd1[t];
    __syncthreads();
    int w = t >> 5, l = t & 31, c = 2 * l;
    for (int row = blockIdx.x * 8 + w; row < NN; row += gridDim.x * 8) {
        float2 rv = *(const float2*)&g_hfinal[row * HH + c];
        rows[w][c] = rv.x; rows[w][c + 1] = rv.y;
        __syncwarp();
        float ax = 0.f, ay = 0.f;
        float bx = b1s[c], by = b1s[c + 1];
#pragma unroll
        for (int j = 0; j < HH; j++) {
            float r = rows[w][j];
            float2 wa = *(const float2*)&Wa[j * HH + c];
            float2 wb = *(const float2*)&Wb[j * HH + c];
            ax += r * wa.x; ay += r * wa.y;
            bx += r * wb.x; by += r * wb.y;
        }
        __syncwarp();
        *(float2*)&g_pa[row * HH + c] = make_float2(ax, ay);
        *(float2*)&g_pb[row * HH + c] = make_float2(bx, by);
    }
}

// ---------------- edge decoder (factorized) ----------------
struct SDec2 {
    float W1c[5 * HH];    // edge_attr rows of Wd1 (128..132)
    float W1d[4 * HH];    // edge_seq rows (133..136)
    float W2[HH * 32];
    float W3[32];
    float b2[32];
    float b3;
    float z1[8][HH];
};

__global__ __launch_bounds__(256) void k_dec(
    const int* __restrict__ ei,
    const float* __restrict__ edge_attr, const float* __restrict__ edge_seq,
    const float* __restrict__ Wd1,
    const float* __restrict__ Wd2, const float* __restrict__ bd2,
    const float* __restrict__ Wd3, const float* __restrict__ bd3,
    float* __restrict__ out) {
    extern __shared__ char smem_raw[];
    SDec2& s = *reinterpret_cast<SDec2*>(smem_raw);
    int t = threadIdx.x, w = t >> 5, l = t & 31;
    for (int i = t; i < 5 * HH; i += 256) s.W1c[i] = Wd1[(2 * HH) * HH + i];
    for (int i = t; i < 4 * HH; i += 256) s.W1d[i] = Wd1[(2 * HH + 5) * HH + i];
    for (int i = t; i < HH * 32; i += 256) s.W2[i] = Wd2[i];
    if (t < 32) { s.W3[t] = Wd3[t]; s.b2[t] = bd2[t]; }
    if (t == 0) s.b3 = bd3[0];
    __syncthreads();
    float* z1 = s.z1[w];
    int c = 2 * l;
    for (int e = blockIdx.x * 8 + w; e < MM; e += gridDim.x * 8) {
        int src = ei[e], dst = ei[MM + e];
        float2 pav = *(const float2*)&g_pa[src * HH + c];
        float2 pbv = *(const float2*)&g_pb[dst * HH + c];
        float zx = pav.x + pbv.x, zy = pav.y + pbv.y;
#pragma unroll
        for (int j = 0; j < 5; j++) {
            float ev = __ldg(&edge_attr[e * 5 + j]);
            float2 wv = *(const float2*)&s.W1c[j * HH + c];
            zx += ev * wv.x; zy += ev * wv.y;
        }
#pragma unroll
        for (int j = 0; j < 4; j++) {
            float ev = __ldg(&edge_seq[e * (KK * 4) + (KK - 1) * 4 + j]);
            float2 wv = *(const float2*)&s.W1d[j * HH + c];
            zx += ev * wv.x; zy += ev * wv.y;
        }
        z1[c] = fmaxf(zx, 0.f);
        z1[c + 1] = fmaxf(zy, 0.f);
        __syncwarp();
        float a2 = s.b2[l];
#pragma unroll
        for (int j = 0; j < HH; j++) a2 += z1[j] * s.W2[j * 32 + l];
        a2 = fmaxf(a2, 0.f);
        float p = a2 * s.W3[l];
#pragma unroll
        for (int off = 16; off > 0; off >>= 1) p += __shfl_down_sync(0xffffffffu, p, off);
        if (l == 0) out[e] = p + s.b3;
        __syncwarp();
    }
}

// ---------------- launch ----------------
extern "C" void kernel_launch(void* const* d_in, const int* in_sizes, int n_in,
                              void* d_out, int out_size) {
    const float* x        = (const float*)d_in[0];
    const int*   ei       = (const int*)  d_in[1];
    const float* eattr    = (const float*)d_in[2];
    const float* u        = (const float*)d_in[3];
    const float* eseq     = (const float*)d_in[4];
    const float* useq     = (const float*)d_in[5];
    const float* W_proj   = (const float*)d_in[6];
    const float* b_proj   = (const float*)d_in[7];
    const float* W_gcn    = (const float*)d_in[8];
    const float* b_gcn    = (const float*)d_in[9];
    const float* Wq       = (const float*)d_in[10];
    const float* bq       = (const float*)d_in[11];
    const float* Wk       = (const float*)d_in[12];
    const float* bk       = (const float*)d_in[13];
    const float* Wv       = (const float*)d_in[14];
    const float* bv       = (const float*)d_in[15];
    const float* Wo       = (const float*)d_in[16];
    const float* bo       = (const float*)d_in[17];
    const float* ln1g     = (const float*)d_in[18];
    const float* ln1b     = (const float*)d_in[19];
    const float* W_ff1    = (const float*)d_in[20];
    const float* b_ff1    = (const float*)d_in[21];
    const float* W_ff2    = (const float*)d_in[22];
    const float* b_ff2    = (const float*)d_in[23];
    const float* ln2g     = (const float*)d_in[24];
    const float* ln2b     = (const float*)d_in[25];
    const float* Wd1      = (const float*)d_in[26];
    const float* bd1      = (const float*)d_in[27];
    const float* Wd2      = (const float*)d_in[28];
    const float* bd2      = (const float*)d_in[29];
    const float* Wd3      = (const float*)d_in[30];
    const float* bd3      = (const float*)d_in[31];
    float* out = (float*)d_out;

    cudaFuncSetAttribute(k_attn, cudaFuncAttributeMaxDynamicSharedMemorySize, (int)sizeof(SAttn));
    cudaFuncSetAttribute(k_ff,   cudaFuncAttributeMaxDynamicSharedMemorySize, (int)sizeof(SFF));
    cudaFuncSetAttribute(k_dec,  cudaFuncAttributeMaxDynamicSharedMemorySize, (int)sizeof(SDec2));

    k_zero_counts<<<(NN + 255) / 256, 256>>>();
    k_count<<<(MM + 255) / 256, 256>>>(ei);
    k_dinv<<<(NN + 255) / 256, 256>>>();
    k_scan<<<1, 1024>>>();
    k_fill<<<(MM + 255) / 256, 256>>>(ei);
    k_ck<<<1, 64>>>(W_proj, b_proj, u, useq);
    k_proj<<<NN / 4, 256>>>(x, W_proj);
    k_aggregate<<<NN, 192>>>();
    k_gcn<<<1184, 256>>>(W_gcn, b_gcn);
    k_attn<<<1332, 256, sizeof(SAttn)>>>(Wq, bq, Wk, bk, Wv, bv, Wo, bo, ln1g, ln1b);
    k_ff<<<1184, 256, sizeof(SFF)>>>(W_ff1, b_ff1, W_ff2, b_ff2, ln2g, ln2b);
    k_predec<<<1184, 256>>>(Wd1, bd1);
    k_dec<<<2048, 256, sizeof(SDec2)>>>(ei, eattr, eseq, Wd1, Wd2, bd2, Wd3, bd3, out);
}

// round 3
// speedup vs baseline: 2.0671x; 1.6395x over previous
#include <cuda_runtime.h>
#include <math.h>

#define NN 100000
#define MM 800000
#define KK 6
#define HH 64
#define NHD 4
#define DHD 16
#define NBLK 98   // ceil(NN/1024)

// ---------------- scratch (device globals; allocation-free) ----------------
__device__ float g_h[NN * KK * HH];      // proj output (tanh)
__device__ float g_agg[NN * KK * HH];    // aggregated h
__device__ float g_h2[NN * KK * HH];     // post-GCN relu
__device__ float g_kv[NN * KK * 2 * HH]; // per (n,k) row: [k(64) | v(64)]
__device__ float g_q[NN * HH];           // q of row k=5
__device__ float g_hmid[NN * HH];        // post-attn LN1 (row k=5 only)
__device__ float g_hfinal[NN * HH];      // post-FF LN2 (row k=5 only)
__device__ float g_pa[NN * HH];          // h_final @ Wd1[0:64]
__device__ float g_pb[NN * HH];          // h_final @ Wd1[64:128] + b1
__device__ float g_dinv[NN];
__device__ int   g_counts[NN];
__device__ int   g_scan[NN];
__device__ int   g_blocksum[128];
__device__ int   g_blockoff[128];
__device__ int   g_rowstart[NN + 1];
__device__ int   g_cursor[NN];
__device__ int   g_srclist[MM];
__device__ float g_ck[KK * HH];

// ---------------- small utility kernels ----------------
__global__ void k_zero_counts() {
    int i = blockIdx.x * blockDim.x + threadIdx.x;
    if (i < NN) g_counts[i] = 0;
}

__global__ void k_count(const int* __restrict__ ei) {
    int e = blockIdx.x * blockDim.x + threadIdx.x;
    if (e < MM) atomicAdd(&g_counts[ei[MM + e]], 1);
}

__global__ void k_dinv() {
    int n = blockIdx.x * blockDim.x + threadIdx.x;
    if (n < NN) g_dinv[n] = rsqrtf((float)g_counts[n] + 1.0f);
}

// ---------------- coalesced 3-phase scan ----------------
__global__ __launch_bounds__(1024) void k_blockscan() {
    __shared__ int warpsums[32];
    int t = threadIdx.x, lane = t & 31, w = t >> 5;
    int i = blockIdx.x * 1024 + t;
    int v0 = (i < NN) ? g_counts[i] : 0;
    int v = v0;
#pragma unroll
    for (int off = 1; off < 32; off <<= 1) {
        int x = __shfl_up_sync(0xffffffffu, v, off);
        if (lane >= off) v += x;
    }
    if (lane == 31) warpsums[w] = v;
    __syncthreads();
    if (w == 0) {
        int s = warpsums[lane];
#pragma unroll
        for (int off = 1; off < 32; off <<= 1) {
            int x = __shfl_up_sync(0xffffffffu, s, off);
            if (lane >= off) s += x;
        }
        warpsums[lane] = s;
    }
    __syncthreads();
    int incl = v + (w > 0 ? warpsums[w - 1] : 0);
    if (i < NN) g_scan[i] = incl;
    if (t == 1023) g_blocksum[blockIdx.x] = incl;
}

__global__ void k_scan2() {
    __shared__ int warpsums[4];
    int t = threadIdx.x, lane = t & 31, w = t >> 5;
    int v0 = (t < NBLK) ? g_blocksum[t] : 0;
    int v = v0;
#pragma unroll
    for (int off = 1; off < 32; off <<= 1) {
        int x = __shfl_up_sync(0xffffffffu, v, off);
        if (lane >= off) v += x;
    }
    if (lane == 31) warpsums[w] = v;
    __syncthreads();
    int base = 0;
    for (int j = 0; j < w; j++) base += warpsums[j];
    int incl = v + base;
    if (t < NBLK) g_blockoff[t] = incl - v0;
    if (t == NBLK - 1) g_rowstart[NN] = incl;
}

__global__ void k_apply() {
    int i = blockIdx.x * blockDim.x + threadIdx.x;
    if (i < NN) {
        int excl = g_scan[i] - g_counts[i] + g_blockoff[i >> 10];
        g_rowstart[i] = excl;
        g_cursor[i]   = excl;
    }
}

__global__ void k_fill(const int* __restrict__ ei) {
    int e = blockIdx.x * blockDim.x + threadIdx.x;
    if (e < MM) {
        int d = ei[MM + e];
        int p = atomicAdd(&g_cursor[d], 1);
        g_srclist[p] = ei[e];
    }
}

// c[k][c] = b_proj[c] + sum_j u[j]*Wp[12+j][c] + sum_j u_seq[k][j]*Wp[23+j][c]
__global__ void k_ck(const float* __restrict__ W_proj, const float* __restrict__ b_proj,
                     const float* __restrict__ u, const float* __restrict__ u_seq) {
    int c = threadIdx.x;
    if (c >= HH) return;
    float base = b_proj[c];
#pragma unroll
    for (int j = 0; j < 11; j++) base += u[j] * W_proj[(12 + j) * HH + c];
    for (int k = 0; k < KK; k++) {
        float val = base;
#pragma unroll
        for (int j = 0; j < 5; j++) val += u_seq[k * 5 + j] * W_proj[(23 + j) * HH + c];
        g_ck[k * HH + c] = val;
    }
}

// ---------------- projection ----------------
__global__ __launch_bounds__(256) void k_proj(const float* __restrict__ x,
                                              const float* __restrict__ W_proj) {
    __shared__ float Wp12[12 * HH];
    __shared__ float cks[KK * HH];
    int t = threadIdx.x;
    for (int i = t; i < 12 * HH; i += 256) Wp12[i] = W_proj[i];
    for (int i = t; i < KK * HH; i += 256) cks[i] = g_ck[i];
    __syncthreads();
    int g = t >> 6, c = t & 63;
    int n = blockIdx.x * 4 + g;
    float s = 0.f;
#pragma unroll
    for (int j = 0; j < 12; j++) s += __ldg(&x[n * 12 + j]) * Wp12[j * HH + c];
    int base = n * (KK * HH) + c;
#pragma unroll
    for (int k = 0; k < KK; k++) g_h[base + k * HH] = tanhf(s + cks[k * HH + c]);
}

// ---------------- aggregation ----------------
__global__ __launch_bounds__(192) void k_aggregate() {
    int n = blockIdx.x;
    int w = threadIdx.x >> 5;
    int l = threadIdx.x & 31;
    float dn = g_dinv[n];
    float selfw = dn * dn;
    int s0 = g_rowstart[n], s1 = g_rowstart[n + 1];
    const float2* hself = (const float2*)&g_h[n * (KK * HH) + w * HH];
    float2 hv = hself[l];
    float accx = hv.x * selfw, accy = hv.y * selfw;
    for (int i = s0; i < s1; i++) {
        int sn = g_srclist[i];
        float wg = g_dinv[sn] * dn;
        float2 v = *(const float2*)&g_h[sn * (KK * HH) + w * HH + 2 * l];
        accx += v.x * wg;
        accy += v.y * wg;
    }
    float2* outp = (float2*)&g_agg[n * (KK * HH) + w * HH];
    outp[l] = make_float2(accx, accy);
}

// ---------------- GCN: 4-row tiled GEMV, h2 = relu(agg @ W_gcn + b_gcn) ----------------
__global__ __launch_bounds__(256) void k_gcn(const float* __restrict__ W_gcn,
                                             const float* __restrict__ b_gcn) {
    __shared__ float Wg[HH * HH];
    __shared__ float bg[HH];
    __shared__ float rows[8][4][HH];
    int t = threadIdx.x;
    for (int i = t; i < HH * HH; i += 256) Wg[i] = W_gcn[i];
    if (t < HH) bg[t] = b_gcn[t];
    __syncthreads();
    int w = t >> 5, l = t & 31, c = 2 * l;
    const int NT = (NN * KK) / 4;   // 150000 4-row tasks
    for (int task = blockIdx.x * 8 + w; task < NT; task += gridDim.x * 8) {
        int r0 = task * 4;
#pragma unroll
        for (int r = 0; r < 4; r++) {
            float2 rv = *(const float2*)&g_agg[(r0 + r) * HH + c];
            rows[w][r][c] = rv.x; rows[w][r][c + 1] = rv.y;
        }
        __syncwarp();
        float a0x = bg[c], a0y = bg[c + 1];
        float a1x = a0x, a1y = a0y, a2x = a0x, a2y = a0y, a3x = a0x, a3y = a0y;
#pragma unroll
        for (int j = 0; j < HH; j++) {
            float2 wv = *(const float2*)&Wg[j * HH + c];
            float v0 = rows[w][0][j], v1 = rows[w][1][j];
            float v2 = rows[w][2][j], v3 = rows[w][3][j];
            a0x += v0 * wv.x; a0y += v0 * wv.y;
            a1x += v1 * wv.x; a1y += v1 * wv.y;
            a2x += v2 * wv.x; a2y += v2 * wv.y;
            a3x += v3 * wv.x; a3y += v3 * wv.y;
        }
        __syncwarp();
        *(float2*)&g_h2[(r0 + 0) * HH + c] = make_float2(fmaxf(a0x, 0.f), fmaxf(a0y, 0.f));
        *(float2*)&g_h2[(r0 + 1) * HH + c] = make_float2(fmaxf(a1x, 0.f), fmaxf(a1y, 0.f));
        *(float2*)&g_h2[(r0 + 2) * HH + c] = make_float2(fmaxf(a2x, 0.f), fmaxf(a2y, 0.f));
        *(float2*)&g_h2[(r0 + 3) * HH + c] = make_float2(fmaxf(a3x, 0.f), fmaxf(a3y, 0.f));
    }
}

// ---------------- QKV dense: kv[row][0:64]=k, [64:128]=v, 2-row x 4-col tiling ------
__global__ __launch_bounds__(256) void k_qkv(
    const float* __restrict__ Wk, const float* __restrict__ bk,
    const float* __restrict__ Wv, const float* __restrict__ bv) {
    __shared__ float Wkv[HH * 128];
    __shared__ float bkv[128];
    __shared__ float rows[8][2][HH];
    int t = threadIdx.x;
    for (int i = t; i < HH * HH; i += 256) {
        int j = i >> 6, c = i & 63;
        Wkv[j * 128 + c]      = Wk[i];
        Wkv[j * 128 + 64 + c] = Wv[i];
    }
    if (t < 64) { bkv[t] = bk[t]; bkv[64 + t] = bv[t]; }
    __syncthreads();
    int w = t >> 5, l = t & 31, c4 = 4 * l;
    float4 bias = *(const float4*)&bkv[c4];
    const int NT = (NN * KK) / 2;   // 300000 2-row tasks
    for (int task = blockIdx.x * 8 + w; task < NT; task += gridDim.x * 8) {
        int r0 = task * 2;
        {
            float2 v0 = *(const float2*)&g_h2[(r0 + 0) * HH + 2 * l];
            float2 v1 = *(const float2*)&g_h2[(r0 + 1) * HH + 2 * l];
            rows[w][0][2 * l] = v0.x; rows[w][0][2 * l + 1] = v0.y;
            rows[w][1][2 * l] = v1.x; rows[w][1][2 * l + 1] = v1.y;
        }
        __syncwarp();
        float a0x = bias.x, a0y = bias.y, a0z = bias.z, a0w = bias.w;
        float a1x = bias.x, a1y = bias.y, a1z = bias.z, a1w = bias.w;
#pragma unroll
        for (int j = 0; j < HH; j++) {
            float4 wv = *(const float4*)&Wkv[j * 128 + c4];
            float v0 = rows[w][0][j], v1 = rows[w][1][j];
            a0x += v0 * wv.x; a0y += v0 * wv.y; a0z += v0 * wv.z; a0w += v0 * wv.w;
            a1x += v1 * wv.x; a1y += v1 * wv.y; a1z += v1 * wv.z; a1w += v1 * wv.w;
        }
        __syncwarp();
        *(float4*)&g_kv[(r0 + 0) * 128 + c4] = make_float4(a0x, a0y, a0z, a0w);
        *(float4*)&g_kv[(r0 + 1) * 128 + c4] = make_float4(a1x, a1y, a1z, a1w);
    }
}

// ---------------- q for row k=5 only: 4-row tiled ----------------
__global__ __launch_bounds__(256) void k_q(const float* __restrict__ Wq,
                                           const float* __restrict__ bq) {
    __shared__ float Wg[HH * HH];
    __shared__ float bg[HH];
    __shared__ float rows[8][4][HH];
    int t = threadIdx.x;
    for (int i = t; i < HH * HH; i += 256) Wg[i] = Wq[i];
    if (t < HH) bg[t] = bq[t];
    __syncthreads();
    int w = t >> 5, l = t & 31, c = 2 * l;
    const int NT = NN / 4;   // 25000
    for (int task = blockIdx.x * 8 + w; task < NT; task += gridDim.x * 8) {
        int n0 = task * 4;
#pragma unroll
        for (int r = 0; r < 4; r++) {
            float2 rv = *(const float2*)&g_h2[((n0 + r) * KK + (KK - 1)) * HH + c];
            rows[w][r][c] = rv.x; rows[w][r][c + 1] = rv.y;
        }
        __syncwarp();
        float a0x = bg[c], a0y = bg[c + 1];
        float a1x = a0x, a1y = a0y, a2x = a0x, a2y = a0y, a3x = a0x, a3y = a0y;
#pragma unroll
        for (int j = 0; j < HH; j++) {
            float2 wv = *(const float2*)&Wg[j * HH + c];
            float v0 = rows[w][0][j], v1 = rows[w][1][j];
            float v2 = rows[w][2][j], v3 = rows[w][3][j];
            a0x += v0 * wv.x; a0y += v0 * wv.y;
            a1x += v1 * wv.x; a1y += v1 * wv.y;
            a2x += v2 * wv.x; a2y += v2 * wv.y;
            a3x += v3 * wv.x; a3y += v3 * wv.y;
        }
        __syncwarp();
        *(float2*)&g_q[(n0 + 0) * HH + c] = make_float2(a0x, a0y);
        *(float2*)&g_q[(n0 + 1) * HH + c] = make_float2(a1x, a1y);
        *(float2*)&g_q[(n0 + 2) * HH + c] = make_float2(a2x, a2y);
        *(float2*)&g_q[(n0 + 3) * HH + c] = make_float2(a3x, a3y);
    }
}

// ---------------- per-node attention tail + LN1 (warp per node) ----------------
__global__ __launch_bounds__(256) void k_attn2(
    const float* __restrict__ Wo, const float* __restrict__ bo,
    const float* __restrict__ ln1g, const float* __restrict__ ln1b) {
    __shared__ float Wo_s[HH * HH];
    __shared__ float bo_s[HH], g1_s[HH], b1_s[HH];
    __shared__ float qv[8][HH];
    __shared__ float kvb[8][KK * 128];
    __shared__ float aw[8][NHD * KK];
    __shared__ float ao[8][HH];
    int t = threadIdx.x, w = t >> 5, l = t & 31;
    for (int i = t; i < HH * HH; i += 256) Wo_s[i] = Wo[i];
    if (t < HH) { bo_s[t] = bo[t]; g1_s[t] = ln1g[t]; b1_s[t] = ln1b[t]; }
    __syncthreads();
    for (int n = blockIdx.x * 8 + w; n < NN; n += gridDim.x * 8) {
        // load q and kv into per-warp smem
        qv[w][l]      = g_q[n * HH + l];
        qv[w][l + 32] = g_q[n * HH + 32 + l];
#pragma unroll
        for (int r = 0; r < KK; r++) {
            float4 v = *(const float4*)&g_kv[(n * KK + r) * 128 + 4 * l];
            *(float4*)&kvb[w][r * 128 + 4 * l] = v;
        }
        __syncwarp();
        // scores + softmax: lanes 0..23 compute one score each, lanes 0..3 softmax
        float sc = 0.f;
        int hh = l / KK, kk = l - hh * KK;
        if (l < NHD * KK) {
#pragma unroll
            for (int d = 0; d < DHD; d++)
                sc += qv[w][hh * DHD + d] * kvb[w][kk * 128 + hh * DHD + d];
            sc *= 0.25f;
        }
        // gather the 6 scores for head (lane<4) via shuffles from lanes h*6+kk
        float mysc[KK];
#pragma unroll
        for (int j = 0; j < KK; j++)
            mysc[j] = __shfl_sync(0xffffffffu, sc, (l & 3) * KK + j);
        if (l < NHD) {
            float mx = mysc[0];
#pragma unroll
            for (int j = 1; j < KK; j++) mx = fmaxf(mx, mysc[j]);
            float sum = 0.f;
#pragma unroll
            for (int j = 0; j < KK; j++) { mysc[j] = expf(mysc[j] - mx); sum += mysc[j]; }
            float inv = 1.0f / sum;
#pragma unroll
            for (int j = 0; j < KK; j++) aw[w][l * KK + j] = mysc[j] * inv;
        }
        __syncwarp();
        // AV: lane covers cols c=2l, 2l+1 (same head)
        int c = 2 * l;
        int hd = l >> 3;
        float a0 = 0.f, a1 = 0.f;
#pragma unroll
        for (int j = 0; j < KK; j++) {
            float wgt = aw[w][hd * KK + j];
            float2 vv = *(const float2*)&kvb[w][j * 128 + 64 + c];
            a0 += wgt * vv.x; a1 += wgt * vv.y;
        }
        ao[w][c] = a0; ao[w][c + 1] = a1;
        __syncwarp();
        // Wo GEMV + residual
        float ox = bo_s[c], oy = bo_s[c + 1];
#pragma unroll
        for (int j = 0; j < HH; j++) {
            float av = ao[w][j];
            float2 wv = *(const float2*)&Wo_s[j * HH + c];
            ox += av * wv.x; oy += av * wv.y;
        }
        float2 hres = *(const float2*)&g_h2[(n * KK + (KK - 1)) * HH + c];
        float y0 = hres.x + ox, y1 = hres.y + oy;
        // LN over 64 (warp butterfly)
        float s1 = y0 + y1, s2 = y0 * y0 + y1 * y1;
#pragma unroll
        for (int off = 16; off > 0; off >>= 1) {
            s1 += __shfl_xor_sync(0xffffffffu, s1, off);
            s2 += __shfl_xor_sync(0xffffffffu, s2, off);
        }
        float m = s1 * (1.0f / HH);
        float var = s2 * (1.0f / HH) - m * m;
        float rstd = rsqrtf(var + 1e-5f);
        float2 outv = make_float2((y0 - m) * rstd * g1_s[c] + b1_s[c],
                                  (y1 - m) * rstd * g1_s[c + 1] + b1_s[c + 1]);
        *(float2*)&g_hmid[n * HH + c] = outv;
    }
}

// ---------------- FF + LN2 (warp per node) ----------------
struct SFF2 {
    float W1[HH * 2 * HH];
    float W2[2 * HH * HH];
    float bb1[2 * HH], bb2[HH], g2[HH], be2[HH];
    float hm[8][HH];
    float z1[8][2 * HH];
};

__global__ __launch_bounds__(256) void k_ff(
    const float* __restrict__ W_ff1, const float* __restrict__ b_ff1,
    const float* __restrict__ W_ff2, const float* __restrict__ b_ff2,
    const float* __restrict__ ln2g, const float* __restrict__ ln2b) {
    extern __shared__ char smem_raw[];
    SFF2& s = *reinterpret_cast<SFF2*>(smem_raw);
    int t = threadIdx.x, w = t >> 5, l = t & 31;
    for (int i = t; i < HH * 2 * HH; i += 256) { s.W1[i] = W_ff1[i]; s.W2[i] = W_ff2[i]; }
    if (t < 2 * HH) s.bb1[t] = b_ff1[t];
    if (t < HH) { s.bb2[t] = b_ff2[t]; s.g2[t] = ln2g[t]; s.be2[t] = ln2b[t]; }
    __syncthreads();
    int c = 2 * l, c4 = 4 * l;
    for (int n = blockIdx.x * 8 + w; n < NN; n += gridDim.x * 8) {
        float2 hm2 = *(const float2*)&g_hmid[n * HH + c];
        s.hm[w][c] = hm2.x; s.hm[w][c + 1] = hm2.y;
        __syncwarp();
        // z1 = relu(hm @ W1 + b1): 128 outs, 4 per lane
        float4 b4 = *(const float4*)&s.bb1[c4];
        float zx = b4.x, zy = b4.y, zz = b4.z, zw = b4.w;
#pragma unroll
        for (int j = 0; j < HH; j++) {
            float hv = s.hm[w][j];
            float4 wv = *(const float4*)&s.W1[j * 2 * HH + c4];
            zx += hv * wv.x; zy += hv * wv.y; zz += hv * wv.z; zw += hv * wv.w;
        }
        *(float4*)&s.z1[w][c4] = make_float4(fmaxf(zx, 0.f), fmaxf(zy, 0.f),
                                             fmaxf(zz, 0.f), fmaxf(zw, 0.f));
        __syncwarp();
        // out = hm + z1 @ W2 + b2: 64 outs, 2 per lane
        float ax = s.bb2[c], ay = s.bb2[c + 1];
#pragma unroll
        for (int j = 0; j < 2 * HH; j++) {
            float zv = s.z1[w][j];
            float2 wv = *(const float2*)&s.W2[j * HH + c];
            ax += zv * wv.x; ay += zv * wv.y;
        }
        float y0 = hm2.x + ax, y1 = hm2.y + ay;
        float s1 = y0 + y1, s2 = y0 * y0 + y1 * y1;
#pragma unroll
        for (int off = 16; off > 0; off >>= 1) {
            s1 += __shfl_xor_sync(0xffffffffu, s1, off);
            s2 += __shfl_xor_sync(0xffffffffu, s2, off);
        }
        float m = s1 * (1.0f / HH);
        float var = s2 * (1.0f / HH) - m * m;
        float rstd = rsqrtf(var + 1e-5f);
        float2 outv = make_float2((y0 - m) * rstd * s.g2[c] + s.be2[c],
                                  (y1 - m) * rstd * s.g2[c + 1] + s.be2[c + 1]);
        *(float2*)&g_hfinal[n * HH + c] = outv;
    }
}

// ---------------- decoder precompute: pa = h@W1a, pb = h@W1b + b1 ----------------
__global__ __launch_bounds__(256) void k_predec(const float* __restrict__ Wd1,
                                                const float* __restrict__ bd1) {
    __shared__ float Wa[HH * HH];
    __shared__ float Wb[HH * HH];
    __shared__ float b1s[HH];
    __shared__ float rows[8][HH];
    int t = threadIdx.x;
    for (int i = t; i < HH * HH; i += 256) { Wa[i] = Wd1[i]; Wb[i] = Wd1[HH * HH + i]; }
    if (t < HH) b1s[t] = bd1[t];
    __syncthreads();
    int w = t >> 5, l = t & 31, c = 2 * l;
    for (int row = blockIdx.x * 8 + w; row < NN; row += gridDim.x * 8) {
        float2 rv = *(const float2*)&g_hfinal[row * HH + c];
        rows[w][c] = rv.x; rows[w][c + 1] = rv.y;
        __syncwarp();
        float ax = 0.f, ay = 0.f;
        float bx = b1s[c], by = b1s[c + 1];
#pragma unroll
        for (int j = 0; j < HH; j++) {
            float r = rows[w][j];
            float2 wa = *(const float2*)&Wa[j * HH + c];
            float2 wb = *(const float2*)&Wb[j * HH + c];
            ax += r * wa.x; ay += r * wa.y;
            bx += r * wb.x; by += r * wb.y;
        }
        __syncwarp();
        *(float2*)&g_pa[row * HH + c] = make_float2(ax, ay);
        *(float2*)&g_pb[row * HH + c] = make_float2(bx, by);
    }
}

// ---------------- edge decoder (factorized) ----------------
struct SDec2 {
    float W1c[5 * HH];
    float W1d[4 * HH];
    float W2[HH * 32];
    float W3[32];
    float b2[32];
    float b3;
    float z1[8][HH];
};

__global__ __launch_bounds__(256) void k_dec(
    const int* __restrict__ ei,
    const float* __restrict__ edge_attr, const float* __restrict__ edge_seq,
    const float* __restrict__ Wd1,
    const float* __restrict__ Wd2, const float* __restrict__ bd2,
    const float* __restrict__ Wd3, const float* __restrict__ bd3,
    float* __restrict__ out) {
    extern __shared__ char smem_raw[];
    SDec2& s = *reinterpret_cast<SDec2*>(smem_raw);
    int t = threadIdx.x, w = t >> 5, l = t & 31;
    for (int i = t; i < 5 * HH; i += 256) s.W1c[i] = Wd1[(2 * HH) * HH + i];
    for (int i = t; i < 4 * HH; i += 256) s.W1d[i] = Wd1[(2 * HH + 5) * HH + i];
    for (int i = t; i < HH * 32; i += 256) s.W2[i] = Wd2[i];
    if (t < 32) { s.W3[t] = Wd3[t]; s.b2[t] = bd2[t]; }
    if (t == 0) s.b3 = bd3[0];
    __syncthreads();
    float* z1 = s.z1[w];
    int c = 2 * l;
    for (int e = blockIdx.x * 8 + w; e < MM; e += gridDim.x * 8) {
        int src = ei[e], dst = ei[MM + e];
        float2 pav = *(const float2*)&g_pa[src * HH + c];
        float2 pbv = *(const float2*)&g_pb[dst * HH + c];
        float zx = pav.x + pbv.x, zy = pav.y + pbv.y;
#pragma unroll
        for (int j = 0; j < 5; j++) {
            float ev = __ldg(&edge_attr[e * 5 + j]);
            float2 wv = *(const float2*)&s.W1c[j * HH + c];
            zx += ev * wv.x; zy += ev * wv.y;
        }
#pragma unroll
        for (int j = 0; j < 4; j++) {
            float ev = __ldg(&edge_seq[e * (KK * 4) + (KK - 1) * 4 + j]);
            float2 wv = *(const float2*)&s.W1d[j * HH + c];
            zx += ev * wv.x; zy += ev * wv.y;
        }
        z1[c] = fmaxf(zx, 0.f);
        z1[c + 1] = fmaxf(zy, 0.f);
        __syncwarp();
        float a2 = s.b2[l];
#pragma unroll
        for (int j = 0; j < HH; j++) a2 += z1[j] * s.W2[j * 32 + l];
        a2 = fmaxf(a2, 0.f);
        float p = a2 * s.W3[l];
#pragma unroll
        for (int off = 16; off > 0; off >>= 1) p += __shfl_down_sync(0xffffffffu, p, off);
        if (l == 0) out[e] = p + s.b3;
        __syncwarp();
    }
}

// ---------------- launch ----------------
extern "C" void kernel_launch(void* const* d_in, const int* in_sizes, int n_in,
                              void* d_out, int out_size) {
    const float* x        = (const float*)d_in[0];
    const int*   ei       = (const int*)  d_in[1];
    const float* eattr    = (const float*)d_in[2];
    const float* u        = (const float*)d_in[3];
    const float* eseq     = (const float*)d_in[4];
    const float* useq     = (const float*)d_in[5];
    const float* W_proj   = (const float*)d_in[6];
    const float* b_proj   = (const float*)d_in[7];
    const float* W_gcn    = (const float*)d_in[8];
    const float* b_gcn    = (const float*)d_in[9];
    const float* Wq       = (const float*)d_in[10];
    const float* bq       = (const float*)d_in[11];
    const float* Wk       = (const float*)d_in[12];
    const float* bk       = (const float*)d_in[13];
    const float* Wv       = (const float*)d_in[14];
    const float* bv       = (const float*)d_in[15];
    const float* Wo       = (const float*)d_in[16];
    const float* bo       = (const float*)d_in[17];
    const float* ln1g     = (const float*)d_in[18];
    const float* ln1b     = (const float*)d_in[19];
    const float* W_ff1    = (const float*)d_in[20];
    const float* b_ff1    = (const float*)d_in[21];
    const float* W_ff2    = (const float*)d_in[22];
    const float* b_ff2    = (const float*)d_in[23];
    const float* ln2g     = (const float*)d_in[24];
    const float* ln2b     = (const float*)d_in[25];
    const float* Wd1      = (const float*)d_in[26];
    const float* bd1      = (const float*)d_in[27];
    const float* Wd2      = (const float*)d_in[28];
    const float* bd2      = (const float*)d_in[29];
    const float* Wd3      = (const float*)d_in[30];
    const float* bd3      = (const float*)d_in[31];
    float* out = (float*)d_out;

    cudaFuncSetAttribute(k_ff,  cudaFuncAttributeMaxDynamicSharedMemorySize, (int)sizeof(SFF2));
    cudaFuncSetAttribute(k_dec, cudaFuncAttributeMaxDynamicSharedMemorySize, (int)sizeof(SDec2));

    k_zero_counts<<<(NN + 255) / 256, 256>>>();
    k_count<<<(MM + 255) / 256, 256>>>(ei);
    k_dinv<<<(NN + 255) / 256, 256>>>();
    k_blockscan<<<NBLK, 1024>>>();
    k_scan2<<<1, 128>>>();
    k_apply<<<(NN + 255) / 256, 256>>>();
    k_fill<<<(MM + 255) / 256, 256>>>(ei);
    k_ck<<<1, 64>>>(W_proj, b_proj, u, useq);
    k_proj<<<NN / 4, 256>>>(x, W_proj);
    k_aggregate<<<NN, 192>>>();
    k_gcn<<<1184, 256>>>(W_gcn, b_gcn);
    k_qkv<<<1184, 256>>>(Wk, bk, Wv, bv);
    k_q<<<1184, 256>>>(Wq, bq);
    k_attn2<<<1184, 256>>>(Wo, bo, ln1g, ln1b);
    k_ff<<<1184, 256, sizeof(SFF2)>>>(W_ff1, b_ff1, W_ff2, b_ff2, ln2g, ln2b);
    k_predec<<<1184, 256>>>(Wd1, bd1);
    k_dec<<<2048, 256, sizeof(SDec2)>>>(ei, eattr, eseq, Wd1, Wd2, bd2, Wd3, bd3, out);
}

// round 5
// speedup vs baseline: 2.1975x; 1.0631x over previous
#include <cuda_runtime.h>
#include <math.h>

#define NN 100000
#define MM 800000
#define KK 6
#define HH 64
#define NHD 4
#define DHD 16
#define NBLK 98   // ceil(NN/1024)

typedef unsigned long long ull;

// ---------------- packed f32x2 helpers (sm_103a FFMA2 path) ----------------
__device__ __forceinline__ ull pack2(float lo, float hi) {
    ull r;
    asm("mov.b64 %0, {%1, %2};" : "=l"(r) : "f"(lo), "f"(hi));
    return r;
}
__device__ __forceinline__ void ffma2(ull& d, ull a, ull b) {
    asm("fma.rn.f32x2 %0, %1, %2, %0;" : "+l"(d) : "l"(a), "l"(b));
}
__device__ __forceinline__ float2 unpack2(ull v) {
    float lo, hi;
    asm("mov.b64 {%0, %1}, %2;" : "=f"(lo), "=f"(hi) : "l"(v));
    return make_float2(lo, hi);
}

// ---------------- scratch (device globals; allocation-free) ----------------
__device__ float g_h[NN * KK * HH];      // proj output (tanh)
__device__ float g_agg[NN * KK * HH];    // aggregated h
__device__ float g_h2r5[NN * HH];        // post-GCN relu, row k=5 only (residual)
__device__ float g_kv[NN * KK * 2 * HH]; // per (n,k) row: [k(64) | v(64)]
__device__ float g_q[NN * HH];           // q of row k=5
__device__ float g_hfinal[NN * HH];      // post-FF LN2 (row k=5 only)
__device__ float g_pa[NN * HH];          // h_final @ Wd1[0:64]
__device__ float g_pb[NN * HH];          // h_final @ Wd1[64:128] + b1
__device__ float g_dinv[NN];
__device__ int   g_counts[NN];
__device__ int   g_scan[NN];
__device__ int   g_blocksum[128];
__device__ int   g_blockoff[128];
__device__ int   g_rowstart[NN + 1];
__device__ int   g_cursor[NN];
__device__ int   g_srclist[MM];
__device__ float g_ck[KK * HH];

// ---------------- small utility kernels ----------------
__global__ void k_zero_counts() {
    int i = blockIdx.x * blockDim.x + threadIdx.x;
    if (i < NN) g_counts[i] = 0;
}

__global__ void k_count(const int* __restrict__ ei) {
    int e = blockIdx.x * blockDim.x + threadIdx.x;
    if (e < MM) atomicAdd(&g_counts[ei[MM + e]], 1);
}

__global__ void k_dinv() {
    int n = blockIdx.x * blockDim.x + threadIdx.x;
    if (n < NN) g_dinv[n] = rsqrtf((float)g_counts[n] + 1.0f);
}

// ---------------- coalesced 3-phase scan ----------------
__global__ __launch_bounds__(1024) void k_blockscan() {
    __shared__ int warpsums[32];
    int t = threadIdx.x, lane = t & 31, w = t >> 5;
    int i = blockIdx.x * 1024 + t;
    int v0 = (i < NN) ? g_counts[i] : 0;
    int v = v0;
#pragma unroll
    for (int off = 1; off < 32; off <<= 1) {
        int x = __shfl_up_sync(0xffffffffu, v, off);
        if (lane >= off) v += x;
    }
    if (lane == 31) warpsums[w] = v;
    __syncthreads();
    if (w == 0) {
        int s = warpsums[lane];
#pragma unroll
        for (int off = 1; off < 32; off <<= 1) {
            int x = __shfl_up_sync(0xffffffffu, s, off);
            if (lane >= off) s += x;
        }
        warpsums[lane] = s;
    }
    __syncthreads();
    int incl = v + (w > 0 ? warpsums[w - 1] : 0);
    if (i < NN) g_scan[i] = incl;
    if (t == 1023) g_blocksum[blockIdx.x] = incl;
}

__global__ void k_scan2() {
    __shared__ int warpsums[4];
    int t = threadIdx.x, lane = t & 31, w = t >> 5;
    int v0 = (t < NBLK) ? g_blocksum[t] : 0;
    int v = v0;
#pragma unroll
    for (int off = 1; off < 32; off <<= 1) {
        int x = __shfl_up_sync(0xffffffffu, v, off);
        if (lane >= off) v += x;
    }
    if (lane == 31) warpsums[w] = v;
    __syncthreads();
    int base = 0;
    for (int j = 0; j < w; j++) base += warpsums[j];
    int incl = v + base;
    if (t < NBLK) g_blockoff[t] = incl - v0;
    if (t == NBLK - 1) g_rowstart[NN] = incl;
}

__global__ void k_apply() {
    int i = blockIdx.x * blockDim.x + threadIdx.x;
    if (i < NN) {
        int excl = g_scan[i] - g_counts[i] + g_blockoff[i >> 10];
        g_rowstart[i] = excl;
        g_cursor[i]   = excl;
    }
}

__global__ void k_fill(const int* __restrict__ ei) {
    int e = blockIdx.x * blockDim.x + threadIdx.x;
    if (e < MM) {
        int d = ei[MM + e];
        int p = atomicAdd(&g_cursor[d], 1);
        g_srclist[p] = ei[e];
    }
}

// c[k][c] = b_proj[c] + sum_j u[j]*Wp[12+j][c] + sum_j u_seq[k][j]*Wp[23+j][c]
__global__ void k_ck(const float* __restrict__ W_proj, const float* __restrict__ b_proj,
                     const float* __restrict__ u, const float* __restrict__ u_seq) {
    int c = threadIdx.x;
    if (c >= HH) return;
    float base = b_proj[c];
#pragma unroll
    for (int j = 0; j < 11; j++) base += u[j] * W_proj[(12 + j) * HH + c];
    for (int k = 0; k < KK; k++) {
        float val = base;
#pragma unroll
        for (int j = 0; j < 5; j++) val += u_seq[k * 5 + j] * W_proj[(23 + j) * HH + c];
        g_ck[k * HH + c] = val;
    }
}

// ---------------- projection ----------------
__global__ __launch_bounds__(256) void k_proj(const float* __restrict__ x,
                                              const float* __restrict__ W_proj) {
    __shared__ float Wp12[12 * HH];
    __shared__ float cks[KK * HH];
    int t = threadIdx.x;
    for (int i = t; i < 12 * HH; i += 256) Wp12[i] = W_proj[i];
    for (int i = t; i < KK * HH; i += 256) cks[i] = g_ck[i];
    __syncthreads();
    int g = t >> 6, c = t & 63;
    int n = blockIdx.x * 4 + g;
    float s = 0.f;
#pragma unroll
    for (int j = 0; j < 12; j++) s += __ldg(&x[n * 12 + j]) * Wp12[j * HH + c];
    int base = n * (KK * HH) + c;
#pragma unroll
    for (int k = 0; k < KK; k++) g_h[base + k * HH] = tanhf(s + cks[k * HH + c]);
}

// ---------------- aggregation ----------------
__global__ __launch_bounds__(192) void k_aggregate() {
    int n = blockIdx.x;
    int w = threadIdx.x >> 5;
    int l = threadIdx.x & 31;
    float dn = g_dinv[n];
    float selfw = dn * dn;
    int s0 = g_rowstart[n], s1 = g_rowstart[n + 1];
    const float2* hself = (const float2*)&g_h[n * (KK * HH) + w * HH];
    float2 hv = hself[l];
    float accx = hv.x * selfw, accy = hv.y * selfw;
    for (int i = s0; i < s1; i++) {
        int sn = g_srclist[i];
        float wg = g_dinv[sn] * dn;
        float2 v = *(const float2*)&g_h[sn * (KK * HH) + w * HH + 2 * l];
        accx += v.x * wg;
        accy += v.y * wg;
    }
    float2* outp = (float2*)&g_agg[n * (KK * HH) + w * HH];
    outp[l] = make_float2(accx, accy);
}

// ---------------- fused GCN + KV + Q (warp per node) ----------------
struct SG {
    float Wg[HH * HH];     // 16K
    float Wkv[HH * 128];   // 32K
    float Wq[HH * HH];     // 16K
    float bg[HH], bkv[128], bq[HH];
    float arow[8][KK][HH]; // 12K
    float h2s[8][KK][HH];  // 12K
};

__global__ __launch_bounds__(256) void k_gcnqkv(
    const float* __restrict__ W_gcn, const float* __restrict__ b_gcn,
    const float* __restrict__ Wk, const float* __restrict__ bk,
    const float* __restrict__ Wv, const float* __restrict__ bv,
    const float* __restrict__ Wq, const float* __restrict__ bq) {
    extern __shared__ char smem_raw[];
    SG& s = *reinterpret_cast<SG*>(smem_raw);
    int t = threadIdx.x, w = t >> 5, l = t & 31;
    for (int i = t; i < HH * HH; i += 256) {
        s.Wg[i] = W_gcn[i];
        s.Wq[i] = Wq[i];
        int j = i >> 6, c = i & 63;
        s.Wkv[j * 128 + c]      = Wk[i];
        s.Wkv[j * 128 + 64 + c] = Wv[i];
    }
    if (t < HH) { s.bg[t] = b_gcn[t]; s.bq[t] = bq[t]; s.bkv[t] = bk[t]; s.bkv[64 + t] = bv[t]; }
    __syncthreads();
    int c = 2 * l, c4 = 4 * l;
    for (int n = blockIdx.x * 8 + w; n < NN; n += gridDim.x * 8) {
        // stage 0: load 6 agg rows
#pragma unroll
        for (int r = 0; r < KK; r++) {
            float2 v = *(const float2*)&g_agg[(n * KK + r) * HH + c];
            s.arow[w][r][c] = v.x; s.arow[w][r][c + 1] = v.y;
        }
        __syncwarp();
        // stage 1: h2 = relu(agg @ Wg + bg), 6 rows x 2 cols/lane
        {
            float a0 = s.bg[c], a1 = s.bg[c + 1];
            float acc[KK][2];
#pragma unroll
            for (int r = 0; r < KK; r++) { acc[r][0] = a0; acc[r][1] = a1; }
#pragma unroll
            for (int j = 0; j < HH; j++) {
                float2 wv = *(const float2*)&s.Wg[j * HH + c];
#pragma unroll
                for (int r = 0; r < KK; r++) {
                    float v = s.arow[w][r][j];
                    acc[r][0] += v * wv.x; acc[r][1] += v * wv.y;
                }
            }
            __syncwarp();
#pragma unroll
            for (int r = 0; r < KK; r++) {
                float h0 = fmaxf(acc[r][0], 0.f), h1 = fmaxf(acc[r][1], 0.f);
                s.h2s[w][r][c] = h0; s.h2s[w][r][c + 1] = h1;
                if (r == KK - 1)
                    *(float2*)&g_h2r5[n * HH + c] = make_float2(h0, h1);
            }
        }
        __syncwarp();
        // stage 2: kv = h2 @ [Wk|Wv] + b, 6 rows x 4 cols/lane
        {
            float4 bias = *(const float4*)&s.bkv[c4];
            float acc[KK][4];
#pragma unroll
            for (int r = 0; r < KK; r++) {
                acc[r][0] = bias.x; acc[r][1] = bias.y; acc[r][2] = bias.z; acc[r][3] = bias.w;
            }
#pragma unroll
            for (int j = 0; j < HH; j++) {
                float4 wv = *(const float4*)&s.Wkv[j * 128 + c4];
#pragma unroll
                for (int r = 0; r < KK; r++) {
                    float v = s.h2s[w][r][j];
                    acc[r][0] += v * wv.x; acc[r][1] += v * wv.y;
                    acc[r][2] += v * wv.z; acc[r][3] += v * wv.w;
                }
            }
#pragma unroll
            for (int r = 0; r < KK; r++)
                *(float4*)&g_kv[(n * KK + r) * 128 + c4] =
                    make_float4(acc[r][0], acc[r][1], acc[r][2], acc[r][3]);
        }
        // stage 3: q = h2row5 @ Wq + bq
        {
            float q0 = s.bq[c], q1 = s.bq[c + 1];
#pragma unroll
            for (int j = 0; j < HH; j++) {
                float v = s.h2s[w][KK - 1][j];
                float2 wv = *(const float2*)&s.Wq[j * HH + c];
                q0 += v * wv.x; q1 += v * wv.y;
            }
            *(float2*)&g_q[n * HH + c] = make_float2(q0, q1);
        }
        __syncwarp();
    }
}

// ---------------- fused attention tail + LN1 + FF + LN2 (warp per node) ----------------
struct SAF {
    float Wo[HH * HH];       // 16K
    float W1[HH * 2 * HH];   // 32K
    float W2[2 * HH * HH];   // 32K
    float bo[HH], g1[HH], b1[HH];
    float bb1[2 * HH], bb2[HH], g2[HH], be2[HH];
    float kv[8][KK * 128];   // 24K
    float qv[8][HH];
    float aw[8][NHD * KK];
    float ao[8][HH];
    float hm[8][HH];
    float z1[8][2 * HH];
};

__global__ __launch_bounds__(256) void k_attnff(
    const float* __restrict__ Wo, const float* __restrict__ bo,
    const float* __restrict__ ln1g, const float* __restrict__ ln1b,
    const float* __restrict__ W_ff1, const float* __restrict__ b_ff1,
    const float* __restrict__ W_ff2, const float* __restrict__ b_ff2,
    const float* __restrict__ ln2g, const float* __restrict__ ln2b) {
    extern __shared__ char smem_raw[];
    SAF& s = *reinterpret_cast<SAF*>(smem_raw);
    int t = threadIdx.x, w = t >> 5, l = t & 31;
    for (int i = t; i < HH * HH; i += 256) s.Wo[i] = Wo[i];
    for (int i = t; i < HH * 2 * HH; i += 256) { s.W1[i] = W_ff1[i]; s.W2[i] = W_ff2[i]; }
    if (t < HH) {
        s.bo[t] = bo[t]; s.g1[t] = ln1g[t]; s.b1[t] = ln1b[t];
        s.bb2[t] = b_ff2[t]; s.g2[t] = ln2g[t]; s.be2[t] = ln2b[t];
    }
    if (t < 2 * HH) s.bb1[t] = b_ff1[t];
    __syncthreads();
    int c = 2 * l, c4 = 4 * l;
    for (int n = blockIdx.x * 8 + w; n < NN; n += gridDim.x * 8) {
        // load q and kv
        s.qv[w][l]      = g_q[n * HH + l];
        s.qv[w][l + 32] = g_q[n * HH + 32 + l];
#pragma unroll
        for (int r = 0; r < KK; r++) {
            float4 v = *(const float4*)&g_kv[(n * KK + r) * 128 + c4];
            *(float4*)&s.kv[w][r * 128 + c4] = v;
        }
        __syncwarp();
        // scores
        float sc = 0.f;
        int hh = l / KK, kk = l - hh * KK;
        if (l < NHD * KK) {
#pragma unroll
            for (int d = 0; d < DHD; d++)
                sc += s.qv[w][hh * DHD + d] * s.kv[w][kk * 128 + hh * DHD + d];
            sc *= 0.25f;
        }
        float mysc[KK];
#pragma unroll
        for (int j = 0; j < KK; j++)
            mysc[j] = __shfl_sync(0xffffffffu, sc, (l & 3) * KK + j);
        if (l < NHD) {
            float mx = mysc[0];
#pragma unroll
            for (int j = 1; j < KK; j++) mx = fmaxf(mx, mysc[j]);
            float sum = 0.f;
#pragma unroll
            for (int j = 0; j < KK; j++) { mysc[j] = expf(mysc[j] - mx); sum += mysc[j]; }
            float inv = 1.0f / sum;
#pragma unroll
            for (int j = 0; j < KK; j++) s.aw[w][l * KK + j] = mysc[j] * inv;
        }
        __syncwarp();
        // AV
        int hd = l >> 3;
        float a0 = 0.f, a1 = 0.f;
#pragma unroll
        for (int j = 0; j < KK; j++) {
            float wgt = s.aw[w][hd * KK + j];
            float2 vv = *(const float2*)&s.kv[w][j * 128 + 64 + c];
            a0 += wgt * vv.x; a1 += wgt * vv.y;
        }
        s.ao[w][c] = a0; s.ao[w][c + 1] = a1;
        __syncwarp();
        // Wo GEMV + residual + LN1
        float ox = s.bo[c], oy = s.bo[c + 1];
#pragma unroll
        for (int j = 0; j < HH; j++) {
            float av = s.ao[w][j];
            float2 wv = *(const float2*)&s.Wo[j * HH + c];
            ox += av * wv.x; oy += av * wv.y;
        }
        float2 hres = *(const float2*)&g_h2r5[n * HH + c];
        float y0 = hres.x + ox, y1 = hres.y + oy;
        float s1 = y0 + y1, s2 = y0 * y0 + y1 * y1;
#pragma unroll
        for (int off = 16; off > 0; off >>= 1) {
            s1 += __shfl_xor_sync(0xffffffffu, s1, off);
            s2 += __shfl_xor_sync(0xffffffffu, s2, off);
        }
        float m = s1 * (1.0f / HH);
        float var = s2 * (1.0f / HH) - m * m;
        float rstd = rsqrtf(var + 1e-5f);
        float hm0 = (y0 - m) * rstd * s.g1[c] + s.b1[c];
        float hm1 = (y1 - m) * rstd * s.g1[c + 1] + s.b1[c + 1];
        s.hm[w][c] = hm0; s.hm[w][c + 1] = hm1;
        __syncwarp();
        // FF1: z1 = relu(hm @ W1 + b1), 4 outs/lane
        {
            float4 b4 = *(const float4*)&s.bb1[c4];
            float zx = b4.x, zy = b4.y, zz = b4.z, zw = b4.w;
#pragma unroll
            for (int j = 0; j < HH; j++) {
                float hv = s.hm[w][j];
                float4 wv = *(const float4*)&s.W1[j * 2 * HH + c4];
                zx += hv * wv.x; zy += hv * wv.y; zz += hv * wv.z; zw += hv * wv.w;
            }
            *(float4*)&s.z1[w][c4] = make_float4(fmaxf(zx, 0.f), fmaxf(zy, 0.f),
                                                 fmaxf(zz, 0.f), fmaxf(zw, 0.f));
        }
        __syncwarp();
        // FF2 + residual + LN2
        float ax = s.bb2[c], ay = s.bb2[c + 1];
#pragma unroll
        for (int j = 0; j < 2 * HH; j++) {
            float zv = s.z1[w][j];
            float2 wv = *(const float2*)&s.W2[j * HH + c];
            ax += zv * wv.x; ay += zv * wv.y;
        }
        float u0 = hm0 + ax, u1 = hm1 + ay;
        float t1 = u0 + u1, t2 = u0 * u0 + u1 * u1;
#pragma unroll
        for (int off = 16; off > 0; off >>= 1) {
            t1 += __shfl_xor_sync(0xffffffffu, t1, off);
            t2 += __shfl_xor_sync(0xffffffffu, t2, off);
        }
        float m2 = t1 * (1.0f / HH);
        float var2 = t2 * (1.0f / HH) - m2 * m2;
        float rstd2 = rsqrtf(var2 + 1e-5f);
        float2 outv = make_float2((u0 - m2) * rstd2 * s.g2[c] + s.be2[c],
                                  (u1 - m2) * rstd2 * s.g2[c + 1] + s.be2[c + 1]);
        *(float2*)&g_hfinal[n * HH + c] = outv;
        __syncwarp();
    }
}

// ---------------- decoder precompute: pa = h@W1a, pb = h@W1b + b1 ----------------
__global__ __launch_bounds__(256) void k_predec(const float* __restrict__ Wd1,
                                                const float* __restrict__ bd1) {
    __shared__ float Wa[HH * HH];
    __shared__ float Wb[HH * HH];
    __shared__ float b1s[HH];
    __shared__ float rows[8][HH];
    int t = threadIdx.x;
    for (int i = t; i < HH * HH; i += 256) { Wa[i] = Wd1[i]; Wb[i] = Wd1[HH * HH + i]; }
    if (t < HH) b1s[t] = bd1[t];
    __syncthreads();
    int w = t >> 5, l = t & 31, c = 2 * l;
    for (int row = blockIdx.x * 8 + w; row < NN; row += gridDim.x * 8) {
        float2 rv = *(const float2*)&g_hfinal[row * HH + c];
        rows[w][c] = rv.x; rows[w][c + 1] = rv.y;
        __syncwarp();
        float ax = 0.f, ay = 0.f;
        float bx = b1s[c], by = b1s[c + 1];
#pragma unroll
        for (int j = 0; j < HH; j++) {
            float r = rows[w][j];
            float2 wa = *(const float2*)&Wa[j * HH + c];
            float2 wb = *(const float2*)&Wb[j * HH + c];
            ax += r * wa.x; ay += r * wa.y;
            bx += r * wb.x; by += r * wb.y;
        }
        __syncwarp();
        *(float2*)&g_pa[row * HH + c] = make_float2(ax, ay);
        *(float2*)&g_pb[row * HH + c] = make_float2(bx, by);
    }
}

// ---------------- edge decoder (factorized, FFMA2 W2) ----------------
// NOTE: z1 must be 8-byte aligned for the LDS.64 in the FFMA2 loop — keep it
// first in the struct (round-4 crash: z1 at offset 10756 → misaligned ull load).
struct SDec3 {
    float z1[8][HH];      // 2K, offset 0 (8B-aligned)
    float2 W2p[32][32];   // [j][l] = (W2[2j][l], W2[2j+1][l]), 8K
    float W1c[5 * HH];
    float W1d[4 * HH];
    float W3[32];
    float b2[32];
    float b3;
};

__global__ __launch_bounds__(256) void k_dec(
    const int* __restrict__ ei,
    const float* __restrict__ edge_attr, const float* __restrict__ edge_seq,
    const float* __restrict__ Wd1,
    const float* __restrict__ Wd2, const float* __restrict__ bd2,
    const float* __restrict__ Wd3, const float* __restrict__ bd3,
    float* __restrict__ out) {
    extern __shared__ char smem_raw[];
    SDec3& s = *reinterpret_cast<SDec3*>(smem_raw);
    int t = threadIdx.x, w = t >> 5, l = t & 31;
    for (int i = t; i < 5 * HH; i += 256) s.W1c[i] = Wd1[(2 * HH) * HH + i];
    for (int i = t; i < 4 * HH; i += 256) s.W1d[i] = Wd1[(2 * HH + 5) * HH + i];
    for (int i = t; i < 1024; i += 256) {
        int j = i >> 5, ll = i & 31;
        s.W2p[j][ll] = make_float2(Wd2[(2 * j) * 32 + ll], Wd2[(2 * j + 1) * 32 + ll]);
    }
    if (t < 32) { s.W3[t] = Wd3[t]; s.b2[t] = bd2[t]; }
    if (t == 0) s.b3 = bd3[0];
    __syncthreads();
    float* z1 = s.z1[w];
    int c = 2 * l;
    for (int e = blockIdx.x * 8 + w; e < MM; e += gridDim.x * 8) {
        int src = ei[e], dst = ei[MM + e];
        float2 pav = *(const float2*)&g_pa[src * HH + c];
        float2 pbv = *(const float2*)&g_pb[dst * HH + c];
        float zx = pav.x + pbv.x, zy = pav.y + pbv.y;
#pragma unroll
        for (int j = 0; j < 5; j++) {
            float ev = __ldg(&edge_attr[e * 5 + j]);
            float2 wv = *(const float2*)&s.W1c[j * HH + c];
            zx += ev * wv.x; zy += ev * wv.y;
        }
#pragma unroll
        for (int j = 0; j < 4; j++) {
            float ev = __ldg(&edge_seq[e * (KK * 4) + (KK - 1) * 4 + j]);
            float2 wv = *(const float2*)&s.W1d[j * HH + c];
            zx += ev * wv.x; zy += ev * wv.y;
        }
        z1[c] = fmaxf(zx, 0.f);
        z1[c + 1] = fmaxf(zy, 0.f);
        __syncwarp();
        // W2 GEMV via packed f32x2: pair the j dimension
        ull acc = pack2(s.b2[l], 0.f);
#pragma unroll
        for (int j = 0; j < 32; j++) {
            ull z2 = *(const ull*)&z1[2 * j];
            ull w2 = *(const ull*)&s.W2p[j][l];
            ffma2(acc, z2, w2);
        }
        float2 av = unpack2(acc);
        float a2 = fmaxf(av.x + av.y, 0.f);
        float p = a2 * s.W3[l];
#pragma unroll
        for (int off = 16; off > 0; off >>= 1) p += __shfl_down_sync(0xffffffffu, p, off);
        if (l == 0) out[e] = p + s.b3;
        __syncwarp();
    }
}

// ---------------- launch ----------------
extern "C" void kernel_launch(void* const* d_in, const int* in_sizes, int n_in,
                              void* d_out, int out_size) {
    const float* x        = (const float*)d_in[0];
    const int*   ei       = (const int*)  d_in[1];
    const float* eattr    = (const float*)d_in[2];
    const float* u        = (const float*)d_in[3];
    const float* eseq     = (const float*)d_in[4];
    const float* useq     = (const float*)d_in[5];
    const float* W_proj   = (const float*)d_in[6];
    const float* b_proj   = (const float*)d_in[7];
    const float* W_gcn    = (const float*)d_in[8];
    const float* b_gcn    = (const float*)d_in[9];
    const float* Wq       = (const float*)d_in[10];
    const float* bq       = (const float*)d_in[11];
    const float* Wk       = (const float*)d_in[12];
    const float* bk       = (const float*)d_in[13];
    const float* Wv       = (const float*)d_in[14];
    const float* bv       = (const float*)d_in[15];
    const float* Wo       = (const float*)d_in[16];
    const float* bo       = (const float*)d_in[17];
    const float* ln1g     = (const float*)d_in[18];
    const float* ln1b     = (const float*)d_in[19];
    const float* W_ff1    = (const float*)d_in[20];
    const float* b_ff1    = (const float*)d_in[21];
    const float* W_ff2    = (const float*)d_in[22];
    const float* b_ff2    = (const float*)d_in[23];
    const float* ln2g     = (const float*)d_in[24];
    const float* ln2b     = (const float*)d_in[25];
    const float* Wd1      = (const float*)d_in[26];
    const float* bd1      = (const float*)d_in[27];
    const float* Wd2      = (const float*)d_in[28];
    const float* bd2      = (const float*)d_in[29];
    const float* Wd3      = (const float*)d_in[30];
    const float* bd3      = (const float*)d_in[31];
    float* out = (float*)d_out;

    cudaFuncSetAttribute(k_gcnqkv, cudaFuncAttributeMaxDynamicSharedMemorySize, (int)sizeof(SG));
    cudaFuncSetAttribute(k_attnff, cudaFuncAttributeMaxDynamicSharedMemorySize, (int)sizeof(SAF));
    cudaFuncSetAttribute(k_dec,    cudaFuncAttributeMaxDynamicSharedMemorySize, (int)sizeof(SDec3));

    k_zero_counts<<<(NN + 255) / 256, 256>>>();
    k_count<<<(MM + 255) / 256, 256>>>(ei);
    k_dinv<<<(NN + 255) / 256, 256>>>();
    k_blockscan<<<NBLK, 1024>>>();
    k_scan2<<<1, 128>>>();
    k_apply<<<(NN + 255) / 256, 256>>>();
    k_fill<<<(MM + 255) / 256, 256>>>(ei);
    k_ck<<<1, 64>>>(W_proj, b_proj, u, useq);
    k_proj<<<NN / 4, 256>>>(x, W_proj);
    k_aggregate<<<NN, 192>>>();
    k_gcnqkv<<<1184, 256, sizeof(SG)>>>(W_gcn, b_gcn, Wk, bk, Wv, bv, Wq, bq);
    k_attnff<<<1184, 256, sizeof(SAF)>>>(Wo, bo, ln1g, ln1b, W_ff1, b_ff1, W_ff2, b_ff2, ln2g, ln2b);
    k_predec<<<1184, 256>>>(Wd1, bd1);
    k_dec<<<2048, 256, sizeof(SDec3)>>>(ei, eattr, eseq, Wd1, Wd2, bd2, Wd3, bd3, out);
}

// round 6
// speedup vs baseline: 2.2815x; 1.0383x over previous
#include <cuda_runtime.h>
#include <math.h>

#define NN 100000
#define MM 800000
#define KK 6
#define HH 64
#define NHD 4
#define DHD 16
#define NBLK 98   // ceil(NN/1024)
#define WSTR 66   // padded transposed-weight row stride (floats): 264B, 8B-aligned, 2-way max conflict

typedef unsigned long long ull;

// ---------------- packed f32x2 helpers (sm_103a FFMA2 path) ----------------
__device__ __forceinline__ ull pack2(float lo, float hi) {
    ull r;
    asm("mov.b64 %0, {%1, %2};" : "=l"(r) : "f"(lo), "f"(hi));
    return r;
}
__device__ __forceinline__ void ffma2(ull& d, ull a, ull b) {
    asm("fma.rn.f32x2 %0, %1, %2, %0;" : "+l"(d) : "l"(a), "l"(b));
}
__device__ __forceinline__ float2 unpack2(ull v) {
    float lo, hi;
    asm("mov.b64 {%0, %1}, %2;" : "=f"(lo), "=f"(hi) : "l"(v));
    return make_float2(lo, hi);
}
__device__ __forceinline__ float hsum2(ull v) {
    float2 p = unpack2(v);
    return p.x + p.y;
}

// ---------------- scratch (device globals; allocation-free) ----------------
__device__ float g_h[NN * KK * HH];      // proj output (tanh)
__device__ float g_agg[NN * KK * HH];    // aggregated h
__device__ float g_h2r5[NN * HH];        // post-GCN relu, row k=5 only (residual)
__device__ float g_kv[NN * KK * 2 * HH]; // per (n,k) row: [k(64) | v(64)]
__device__ float g_q[NN * HH];           // q of row k=5
__device__ float g_hfinal[NN * HH];      // post-FF LN2 (row k=5 only)
__device__ float g_pa[NN * HH];          // h_final @ Wd1[0:64]
__device__ float g_pb[NN * HH];          // h_final @ Wd1[64:128] + b1
__device__ float g_dinv[NN];
__device__ int   g_counts[NN];
__device__ int   g_scan[NN];
__device__ int   g_blocksum[128];
__device__ int   g_blockoff[128];
__device__ int   g_rowstart[NN + 1];
__device__ int   g_cursor[NN];
__device__ int   g_srclist[MM];
__device__ float g_ck[KK * HH];

// ---------------- small utility kernels ----------------
__global__ void k_zero_counts() {
    int i = blockIdx.x * blockDim.x + threadIdx.x;
    if (i < NN) g_counts[i] = 0;
}

__global__ void k_count(const int* __restrict__ ei) {
    int e = blockIdx.x * blockDim.x + threadIdx.x;
    if (e < MM) atomicAdd(&g_counts[ei[MM + e]], 1);
}

__global__ void k_dinv() {
    int n = blockIdx.x * blockDim.x + threadIdx.x;
    if (n < NN) g_dinv[n] = rsqrtf((float)g_counts[n] + 1.0f);
}

// ---------------- coalesced 3-phase scan ----------------
__global__ __launch_bounds__(1024) void k_blockscan() {
    __shared__ int warpsums[32];
    int t = threadIdx.x, lane = t & 31, w = t >> 5;
    int i = blockIdx.x * 1024 + t;
    int v0 = (i < NN) ? g_counts[i] : 0;
    int v = v0;
#pragma unroll
    for (int off = 1; off < 32; off <<= 1) {
        int x = __shfl_up_sync(0xffffffffu, v, off);
        if (lane >= off) v += x;
    }
    if (lane == 31) warpsums[w] = v;
    __syncthreads();
    if (w == 0) {
        int s = warpsums[lane];
#pragma unroll
        for (int off = 1; off < 32; off <<= 1) {
            int x = __shfl_up_sync(0xffffffffu, s, off);
            if (lane >= off) s += x;
        }
        warpsums[lane] = s;
    }
    __syncthreads();
    int incl = v + (w > 0 ? warpsums[w - 1] : 0);
    if (i < NN) g_scan[i] = incl;
    if (t == 1023) g_blocksum[blockIdx.x] = incl;
}

__global__ void k_scan2() {
    __shared__ int warpsums[4];
    int t = threadIdx.x, lane = t & 31, w = t >> 5;
    int v0 = (t < NBLK) ? g_blocksum[t] : 0;
    int v = v0;
#pragma unroll
    for (int off = 1; off < 32; off <<= 1) {
        int x = __shfl_up_sync(0xffffffffu, v, off);
        if (lane >= off) v += x;
    }
    if (lane == 31) warpsums[w] = v;
    __syncthreads();
    int base = 0;
    for (int j = 0; j < w; j++) base += warpsums[j];
    int incl = v + base;
    if (t < NBLK) g_blockoff[t] = incl - v0;
    if (t == NBLK - 1) g_rowstart[NN] = incl;
}

__global__ void k_apply() {
    int i = blockIdx.x * blockDim.x + threadIdx.x;
    if (i < NN) {
        int excl = g_scan[i] - g_counts[i] + g_blockoff[i >> 10];
        g_rowstart[i] = excl;
        g_cursor[i]   = excl;
    }
}

__global__ void k_fill(const int* __restrict__ ei) {
    int e = blockIdx.x * blockDim.x + threadIdx.x;
    if (e < MM) {
        int d = ei[MM + e];
        int p = atomicAdd(&g_cursor[d], 1);
        g_srclist[p] = ei[e];
    }
}

// c[k][c] = b_proj[c] + sum_j u[j]*Wp[12+j][c] + sum_j u_seq[k][j]*Wp[23+j][c]
__global__ void k_ck(const float* __restrict__ W_proj, const float* __restrict__ b_proj,
                     const float* __restrict__ u, const float* __restrict__ u_seq) {
    int c = threadIdx.x;
    if (c >= HH) return;
    float base = b_proj[c];
#pragma unroll
    for (int j = 0; j < 11; j++) base += u[j] * W_proj[(12 + j) * HH + c];
    for (int k = 0; k < KK; k++) {
        float val = base;
#pragma unroll
        for (int j = 0; j < 5; j++) val += u_seq[k * 5 + j] * W_proj[(23 + j) * HH + c];
        g_ck[k * HH + c] = val;
    }
}

// ---------------- projection ----------------
__global__ __launch_bounds__(256) void k_proj(const float* __restrict__ x,
                                              const float* __restrict__ W_proj) {
    __shared__ float Wp12[12 * HH];
    __shared__ float cks[KK * HH];
    int t = threadIdx.x;
    for (int i = t; i < 12 * HH; i += 256) Wp12[i] = W_proj[i];
    for (int i = t; i < KK * HH; i += 256) cks[i] = g_ck[i];
    __syncthreads();
    int g = t >> 6, c = t & 63;
    int n = blockIdx.x * 4 + g;
    float s = 0.f;
#pragma unroll
    for (int j = 0; j < 12; j++) s += __ldg(&x[n * 12 + j]) * Wp12[j * HH + c];
    int base = n * (KK * HH) + c;
#pragma unroll
    for (int k = 0; k < KK; k++) g_h[base + k * HH] = tanhf(s + cks[k * HH + c]);
}

// ---------------- aggregation ----------------
__global__ __launch_bounds__(192) void k_aggregate() {
    int n = blockIdx.x;
    int w = threadIdx.x >> 5;
    int l = threadIdx.x & 31;
    float dn = g_dinv[n];
    float selfw = dn * dn;
    int s0 = g_rowstart[n], s1 = g_rowstart[n + 1];
    const float2* hself = (const float2*)&g_h[n * (KK * HH) + w * HH];
    float2 hv = hself[l];
    float accx = hv.x * selfw, accy = hv.y * selfw;
    for (int i = s0; i < s1; i++) {
        int sn = g_srclist[i];
        float wg = g_dinv[sn] * dn;
        float2 v = *(const float2*)&g_h[sn * (KK * HH) + w * HH + 2 * l];
        accx += v.x * wg;
        accy += v.y * wg;
    }
    float2* outp = (float2*)&g_agg[n * (KK * HH) + w * HH];
    outp[l] = make_float2(accx, accy);
}

// ---------------- fused GCN + KV + Q (warp per node, FFMA2 j-pairing) ----------------
struct __align__(16) SG {
    float Wgt[HH * WSTR];       // Wgt[c*66+j] = W_gcn[j][c]        16.9K
    float Wkvt[128 * WSTR];     // Wkvt[c*66+j] = [Wk|Wv][j][c]     33.8K
    float Wqt[HH * WSTR];       // 16.9K
    float arow[12][KK][HH];     // row-major (j contiguous)         18K
    float h2s[12][KK][HH];      // 18K
    float bg[HH], bkv[128], bq[HH];
};

__global__ __launch_bounds__(384) void k_gcnqkv(
    const float* __restrict__ W_gcn, const float* __restrict__ b_gcn,
    const float* __restrict__ Wk, const float* __restrict__ bk,
    const float* __restrict__ Wv, const float* __restrict__ bv,
    const float* __restrict__ Wq, const float* __restrict__ bq) {
    extern __shared__ char smem_raw[];
    SG& s = *reinterpret_cast<SG*>(smem_raw);
    int t = threadIdx.x, w = t >> 5, l = t & 31;
    for (int i = t; i < HH * HH; i += 384) {
        int j = i >> 6, c = i & 63;
        s.Wgt[c * WSTR + j] = W_gcn[i];
        s.Wqt[c * WSTR + j] = Wq[i];
        s.Wkvt[c * WSTR + j] = Wk[i];
        s.Wkvt[(c + 64) * WSTR + j] = Wv[i];
    }
    if (t < HH) { s.bg[t] = b_gcn[t]; s.bq[t] = bq[t]; s.bkv[t] = bk[t]; s.bkv[64 + t] = bv[t]; }
    __syncthreads();
    const int c0 = l, c1 = l + 32;
    for (int n = blockIdx.x * 12 + w; n < NN; n += gridDim.x * 12) {
        // load 6 agg rows (row-major, j contiguous)
#pragma unroll
        for (int r = 0; r < KK; r++) {
            float2 v = *(const float2*)&g_agg[(n * KK + r) * HH + 2 * l];
            *(float2*)&s.arow[w][r][2 * l] = v;
        }
        __syncwarp();
        // stage 1: h2 = relu(agg @ Wg + bg) — cols (l, l+32), 6 rows, packed j-pairs
        {
            ull acc[KK][2];
#pragma unroll
            for (int r = 0; r < KK; r++) { acc[r][0] = 0ull; acc[r][1] = 0ull; }
#pragma unroll
            for (int j2 = 0; j2 < 32; j2++) {
                ull w0 = *(const ull*)&s.Wgt[c0 * WSTR + 2 * j2];
                ull w1 = *(const ull*)&s.Wgt[c1 * WSTR + 2 * j2];
#pragma unroll
                for (int r = 0; r < KK; r++) {
                    ull av = *(const ull*)&s.arow[w][r][2 * j2];
                    ffma2(acc[r][0], av, w0);
                    ffma2(acc[r][1], av, w1);
                }
            }
#pragma unroll
            for (int r = 0; r < KK; r++) {
                float h0 = fmaxf(hsum2(acc[r][0]) + s.bg[c0], 0.f);
                float h1 = fmaxf(hsum2(acc[r][1]) + s.bg[c1], 0.f);
                s.h2s[w][r][c0] = h0;
                s.h2s[w][r][c1] = h1;
                if (r == KK - 1) {
                    g_h2r5[n * HH + c0] = h0;
                    g_h2r5[n * HH + c1] = h1;
                }
            }
        }
        __syncwarp();
        // stage 2: kv = h2 @ [Wk|Wv] + b — 4 cols/lane, 6 rows, packed j-pairs
        {
            ull acc[KK][4];
#pragma unroll
            for (int r = 0; r < KK; r++)
#pragma unroll
                for (int q = 0; q < 4; q++) acc[r][q] = 0ull;
#pragma unroll
            for (int j2 = 0; j2 < 32; j2++) {
                ull w0 = *(const ull*)&s.Wkvt[(l)      * WSTR + 2 * j2];
                ull w1 = *(const ull*)&s.Wkvt[(l + 32) * WSTR + 2 * j2];
                ull w2 = *(const ull*)&s.Wkvt[(l + 64) * WSTR + 2 * j2];
                ull w3 = *(const ull*)&s.Wkvt[(l + 96) * WSTR + 2 * j2];
#pragma unroll
                for (int r = 0; r < KK; r++) {
                    ull hv = *(const ull*)&s.h2s[w][r][2 * j2];
                    ffma2(acc[r][0], hv, w0);
                    ffma2(acc[r][1], hv, w1);
                    ffma2(acc[r][2], hv, w2);
                    ffma2(acc[r][3], hv, w3);
                }
            }
#pragma unroll
            for (int r = 0; r < KK; r++) {
                float* kvp = &g_kv[(n * KK + r) * 128];
                kvp[l]      = hsum2(acc[r][0]) + s.bkv[l];
                kvp[l + 32] = hsum2(acc[r][1]) + s.bkv[l + 32];
                kvp[l + 64] = hsum2(acc[r][2]) + s.bkv[l + 64];
                kvp[l + 96] = hsum2(acc[r][3]) + s.bkv[l + 96];
            }
        }
        // stage 3: q = h2row5 @ Wq + bq
        {
            ull a0 = 0ull, a1 = 0ull;
#pragma unroll
            for (int j2 = 0; j2 < 32; j2++) {
                ull hv = *(const ull*)&s.h2s[w][KK - 1][2 * j2];
                ull w0 = *(const ull*)&s.Wqt[c0 * WSTR + 2 * j2];
                ull w1 = *(const ull*)&s.Wqt[c1 * WSTR + 2 * j2];
                ffma2(a0, hv, w0);
                ffma2(a1, hv, w1);
            }
            g_q[n * HH + c0] = hsum2(a0) + s.bq[c0];
            g_q[n * HH + c1] = hsum2(a1) + s.bq[c1];
        }
        __syncwarp();
    }
}

// ---------------- fused attention tail + LN1 + FF + LN2 (warp per node, FFMA2) ------
struct __align__(16) SAF {
    float Wot[HH * WSTR];     // 16.9K   Wot[c*66+j] = Wo[j][c]
    float W1t[128 * WSTR];    // 33.8K   W1t[c*66+j] = W_ff1[j][c]
    float W2t[HH * 130];      // 33.3K   W2t[c*130+j] = W_ff2[j][c], j<128
    float kv[12][KK * 128];   // 36.9K
    float qv[12][HH];
    float ao[12][HH];
    float hm[12][HH];
    float z1[12][2 * HH];
    float aw[12][NHD * KK];
    float bo[HH], g1[HH], b1[HH], bb2[HH], g2[HH], be2[HH];
    float bb1[2 * HH];
};

__global__ __launch_bounds__(384) void k_attnff(
    const float* __restrict__ Wo, const float* __restrict__ bo,
    const float* __restrict__ ln1g, const float* __restrict__ ln1b,
    const float* __restrict__ W_ff1, const float* __restrict__ b_ff1,
    const float* __restrict__ W_ff2, const float* __restrict__ b_ff2,
    const float* __restrict__ ln2g, const float* __restrict__ ln2b) {
    extern __shared__ char smem_raw[];
    SAF& s = *reinterpret_cast<SAF*>(smem_raw);
    int t = threadIdx.x, w = t >> 5, l = t & 31;
    for (int i = t; i < HH * HH; i += 384) {
        int j = i >> 6, c = i & 63;
        s.Wot[c * WSTR + j] = Wo[i];
    }
    for (int i = t; i < HH * 128; i += 384) {
        int j = i >> 7, c = i & 127;
        s.W1t[c * WSTR + j] = W_ff1[i];
    }
    for (int i = t; i < 128 * HH; i += 384) {
        int j = i >> 6, c = i & 63;
        s.W2t[c * 130 + j] = W_ff2[i];
    }
    if (t < HH) {
        s.bo[t] = bo[t]; s.g1[t] = ln1g[t]; s.b1[t] = ln1b[t];
        s.bb2[t] = b_ff2[t]; s.g2[t] = ln2g[t]; s.be2[t] = ln2b[t];
    }
    if (t < 2 * HH) s.bb1[t] = b_ff1[t];
    __syncthreads();
    const int c0 = l, c1 = l + 32;
    int c2 = 2 * l, c4 = 4 * l;
    for (int n = blockIdx.x * 12 + w; n < NN; n += gridDim.x * 12) {
        // load q and kv
        s.qv[w][l]      = g_q[n * HH + l];
        s.qv[w][l + 32] = g_q[n * HH + 32 + l];
#pragma unroll
        for (int r = 0; r < KK; r++) {
            float4 v = *(const float4*)&g_kv[(n * KK + r) * 128 + c4];
            *(float4*)&s.kv[w][r * 128 + c4] = v;
        }
        __syncwarp();
        // scores
        float sc = 0.f;
        int hh = l / KK, kk = l - hh * KK;
        if (l < NHD * KK) {
#pragma unroll
            for (int d = 0; d < DHD; d++)
                sc += s.qv[w][hh * DHD + d] * s.kv[w][kk * 128 + hh * DHD + d];
            sc *= 0.25f;
        }
        float mysc[KK];
#pragma unroll
        for (int j = 0; j < KK; j++)
            mysc[j] = __shfl_sync(0xffffffffu, sc, (l & 3) * KK + j);
        if (l < NHD) {
            float mx = mysc[0];
#pragma unroll
            for (int j = 1; j < KK; j++) mx = fmaxf(mx, mysc[j]);
            float sum = 0.f;
#pragma unroll
            for (int j = 0; j < KK; j++) { mysc[j] = expf(mysc[j] - mx); sum += mysc[j]; }
            float inv = 1.0f / sum;
#pragma unroll
            for (int j = 0; j < KK; j++) s.aw[w][l * KK + j] = mysc[j] * inv;
        }
        __syncwarp();
        // AV (cols 2l, 2l+1 — same head per lane)
        int hd = l >> 3;
        float a0 = 0.f, a1 = 0.f;
#pragma unroll
        for (int j = 0; j < KK; j++) {
            float wgt = s.aw[w][hd * KK + j];
            float2 vv = *(const float2*)&s.kv[w][j * 128 + 64 + c2];
            a0 += wgt * vv.x; a1 += wgt * vv.y;
        }
        s.ao[w][c2] = a0; s.ao[w][c2 + 1] = a1;
        __syncwarp();
        // Wo GEMV (FFMA2, cols l / l+32) + residual + LN1
        ull o0 = 0ull, o1 = 0ull;
#pragma unroll
        for (int j2 = 0; j2 < 32; j2++) {
            ull av = *(const ull*)&s.ao[w][2 * j2];
            ull w0 = *(const ull*)&s.Wot[c0 * WSTR + 2 * j2];
            ull w1 = *(const ull*)&s.Wot[c1 * WSTR + 2 * j2];
            ffma2(o0, av, w0);
            ffma2(o1, av, w1);
        }
        float y0 = g_h2r5[n * HH + c0] + hsum2(o0) + s.bo[c0];
        float y1 = g_h2r5[n * HH + c1] + hsum2(o1) + s.bo[c1];
        float s1 = y0 + y1, s2 = y0 * y0 + y1 * y1;
#pragma unroll
        for (int off = 16; off > 0; off >>= 1) {
            s1 += __shfl_xor_sync(0xffffffffu, s1, off);
            s2 += __shfl_xor_sync(0xffffffffu, s2, off);
        }
        float m = s1 * (1.0f / HH);
        float var = s2 * (1.0f / HH) - m * m;
        float rstd = rsqrtf(var + 1e-5f);
        float hm0 = (y0 - m) * rstd * s.g1[c0] + s.b1[c0];
        float hm1 = (y1 - m) * rstd * s.g1[c1] + s.b1[c1];
        s.hm[w][c0] = hm0; s.hm[w][c1] = hm1;
        __syncwarp();
        // FF1 (FFMA2, 4 cols/lane): z1 = relu(hm @ W1 + b1)
        {
            ull f0 = 0ull, f1 = 0ull, f2 = 0ull, f3 = 0ull;
#pragma unroll
            for (int j2 = 0; j2 < 32; j2++) {
                ull hv = *(const ull*)&s.hm[w][2 * j2];
                ull w0 = *(const ull*)&s.W1t[(l)      * WSTR + 2 * j2];
                ull w1 = *(const ull*)&s.W1t[(l + 32) * WSTR + 2 * j2];
                ull w2 = *(const ull*)&s.W1t[(l + 64) * WSTR + 2 * j2];
                ull w3 = *(const ull*)&s.W1t[(l + 96) * WSTR + 2 * j2];
                ffma2(f0, hv, w0);
                ffma2(f1, hv, w1);
                ffma2(f2, hv, w2);
                ffma2(f3, hv, w3);
            }
            s.z1[w][l]      = fmaxf(hsum2(f0) + s.bb1[l], 0.f);
            s.z1[w][l + 32] = fmaxf(hsum2(f1) + s.bb1[l + 32], 0.f);
            s.z1[w][l + 64] = fmaxf(hsum2(f2) + s.bb1[l + 64], 0.f);
            s.z1[w][l + 96] = fmaxf(hsum2(f3) + s.bb1[l + 96], 0.f);
        }
        __syncwarp();
        // FF2 (FFMA2, cols l / l+32) + residual + LN2
        ull g0 = 0ull, g1a = 0ull;
#pragma unroll
        for (int j2 = 0; j2 < 64; j2++) {
            ull zv = *(const ull*)&s.z1[w][2 * j2];
            ull w0 = *(const ull*)&s.W2t[c0 * 130 + 2 * j2];
            ull w1 = *(const ull*)&s.W2t[c1 * 130 + 2 * j2];
            ffma2(g0, zv, w0);
            ffma2(g1a, zv, w1);
        }
        float u0 = hm0 + hsum2(g0) + s.bb2[c0];
        float u1 = hm1 + hsum2(g1a) + s.bb2[c1];
        float t1 = u0 + u1, t2 = u0 * u0 + u1 * u1;
#pragma unroll
        for (int off = 16; off > 0; off >>= 1) {
            t1 += __shfl_xor_sync(0xffffffffu, t1, off);
            t2 += __shfl_xor_sync(0xffffffffu, t2, off);
        }
        float m2 = t1 * (1.0f / HH);
        float var2 = t2 * (1.0f / HH) - m2 * m2;
        float rstd2 = rsqrtf(var2 + 1e-5f);
        g_hfinal[n * HH + c0] = (u0 - m2) * rstd2 * s.g2[c0] + s.be2[c0];
        g_hfinal[n * HH + c1] = (u1 - m2) * rstd2 * s.g2[c1] + s.be2[c1];
        __syncwarp();
    }
}

// ---------------- decoder precompute (FFMA2): pa = h@W1a, pb = h@W1b + b1 -----------
__global__ __launch_bounds__(256) void k_predec(const float* __restrict__ Wd1,
                                                const float* __restrict__ bd1) {
    __shared__ __align__(16) float Wat[HH * WSTR];
    __shared__ __align__(16) float Wbt[HH * WSTR];
    __shared__ __align__(16) float rows[8][HH];
    __shared__ float b1s[HH];
    int t = threadIdx.x;
    for (int i = t; i < HH * HH; i += 256) {
        int j = i >> 6, c = i & 63;
        Wat[c * WSTR + j] = Wd1[i];
        Wbt[c * WSTR + j] = Wd1[HH * HH + i];
    }
    if (t < HH) b1s[t] = bd1[t];
    __syncthreads();
    int w = t >> 5, l = t & 31;
    const int c0 = l, c1 = l + 32;
    for (int row = blockIdx.x * 8 + w; row < NN; row += gridDim.x * 8) {
        float2 rv = *(const float2*)&g_hfinal[row * HH + 2 * l];
        *(float2*)&rows[w][2 * l] = rv;
        __syncwarp();
        ull a0 = 0ull, a1 = 0ull, b0 = 0ull, b1 = 0ull;
#pragma unroll
        for (int j2 = 0; j2 < 32; j2++) {
            ull v = *(const ull*)&rows[w][2 * j2];
            ull wa0 = *(const ull*)&Wat[c0 * WSTR + 2 * j2];
            ull wa1 = *(const ull*)&Wat[c1 * WSTR + 2 * j2];
            ull wb0 = *(const ull*)&Wbt[c0 * WSTR + 2 * j2];
            ull wb1 = *(const ull*)&Wbt[c1 * WSTR + 2 * j2];
            ffma2(a0, v, wa0);
            ffma2(a1, v, wa1);
            ffma2(b0, v, wb0);
            ffma2(b1, v, wb1);
        }
        g_pa[row * HH + c0] = hsum2(a0);
        g_pa[row * HH + c1] = hsum2(a1);
        g_pb[row * HH + c0] = hsum2(b0) + b1s[c0];
        g_pb[row * HH + c1] = hsum2(b1) + b1s[c1];
        __syncwarp();
    }
}

// ---------------- edge decoder (factorized, FFMA2 W2) ----------------
// NOTE: z1 must be 8-byte aligned for the LDS.64 in the FFMA2 loop — keep it first.
struct __align__(16) SDec3 {
    float z1[8][HH];      // 2K, offset 0 (8B-aligned)
    float2 W2p[32][32];   // [j][l] = (W2[2j][l], W2[2j+1][l]), 8K
    float W1c[5 * HH];
    float W1d[4 * HH];
    float W3[32];
    float b2[32];
    float b3;
};

__global__ __launch_bounds__(256) void k_dec(
    const int* __restrict__ ei,
    const float* __restrict__ edge_attr, const float* __restrict__ edge_seq,
    const float* __restrict__ Wd1,
    const float* __restrict__ Wd2, const float* __restrict__ bd2,
    const float* __restrict__ Wd3, const float* __restrict__ bd3,
    float* __restrict__ out) {
    extern __shared__ char smem_raw[];
    SDec3& s = *reinterpret_cast<SDec3*>(smem_raw);
    int t = threadIdx.x, w = t >> 5, l = t & 31;
    for (int i = t; i < 5 * HH; i += 256) s.W1c[i] = Wd1[(2 * HH) * HH + i];
    for (int i = t; i < 4 * HH; i += 256) s.W1d[i] = Wd1[(2 * HH + 5) * HH + i];
    for (int i = t; i < 1024; i += 256) {
        int j = i >> 5, ll = i & 31;
        s.W2p[j][ll] = make_float2(Wd2[(2 * j) * 32 + ll], Wd2[(2 * j + 1) * 32 + ll]);
    }
    if (t < 32) { s.W3[t] = Wd3[t]; s.b2[t] = bd2[t]; }
    if (t == 0) s.b3 = bd3[0];
    __syncthreads();
    float* z1 = s.z1[w];
    int c = 2 * l;
    for (int e = blockIdx.x * 8 + w; e < MM; e += gridDim.x * 8) {
        int src = ei[e], dst = ei[MM + e];
        float2 pav = *(const float2*)&g_pa[src * HH + c];
        float2 pbv = *(const float2*)&g_pb[dst * HH + c];
        float zx = pav.x + pbv.x, zy = pav.y + pbv.y;
#pragma unroll
        for (int j = 0; j < 5; j++) {
            float ev = __ldg(&edge_attr[e * 5 + j]);
            float2 wv = *(const float2*)&s.W1c[j * HH + c];
            zx += ev * wv.x; zy += ev * wv.y;
        }
#pragma unroll
        for (int j = 0; j < 4; j++) {
            float ev = __ldg(&edge_seq[e * (KK * 4) + (KK - 1) * 4 + j]);
            float2 wv = *(const float2*)&s.W1d[j * HH + c];
            zx += ev * wv.x; zy += ev * wv.y;
        }
        z1[c] = fmaxf(zx, 0.f);
        z1[c + 1] = fmaxf(zy, 0.f);
        __syncwarp();
        ull acc = pack2(s.b2[l], 0.f);
#pragma unroll
        for (int j = 0; j < 32; j++) {
            ull z2 = *(const ull*)&z1[2 * j];
            ull w2 = *(const ull*)&s.W2p[j][l];
            ffma2(acc, z2, w2);
        }
        float2 av = unpack2(acc);
        float a2 = fmaxf(av.x + av.y, 0.f);
        float p = a2 * s.W3[l];
#pragma unroll
        for (int off = 16; off > 0; off >>= 1) p += __shfl_down_sync(0xffffffffu, p, off);
        if (l == 0) out[e] = p + s.b3;
        __syncwarp();
    }
}

// ---------------- launch ----------------
extern "C" void kernel_launch(void* const* d_in, const int* in_sizes, int n_in,
                              void* d_out, int out_size) {
    const float* x        = (const float*)d_in[0];
    const int*   ei       = (const int*)  d_in[1];
    const float* eattr    = (const float*)d_in[2];
    const float* u        = (const float*)d_in[3];
    const float* eseq     = (const float*)d_in[4];
    const float* useq     = (const float*)d_in[5];
    const float* W_proj   = (const float*)d_in[6];
    const float* b_proj   = (const float*)d_in[7];
    const float* W_gcn    = (const float*)d_in[8];
    const float* b_gcn    = (const float*)d_in[9];
    const float* Wq       = (const float*)d_in[10];
    const float* bq       = (const float*)d_in[11];
    const float* Wk       = (const float*)d_in[12];
    const float* bk       = (const float*)d_in[13];
    const float* Wv       = (const float*)d_in[14];
    const float* bv       = (const float*)d_in[15];
    const float* Wo       = (const float*)d_in[16];
    const float* bo       = (const float*)d_in[17];
    const float* ln1g     = (const float*)d_in[18];
    const float* ln1b     = (const float*)d_in[19];
    const float* W_ff1    = (const float*)d_in[20];
    const float* b_ff1    = (const float*)d_in[21];
    const float* W_ff2    = (const float*)d_in[22];
    const float* b_ff2    = (const float*)d_in[23];
    const float* ln2g     = (const float*)d_in[24];
    const float* ln2b     = (const float*)d_in[25];
    const float* Wd1      = (const float*)d_in[26];
    const float* bd1      = (const float*)d_in[27];
    const float* Wd2      = (const float*)d_in[28];
    const float* bd2      = (const float*)d_in[29];
    const float* Wd3      = (const float*)d_in[30];
    const float* bd3      = (const float*)d_in[31];
    float* out = (float*)d_out;

    cudaFuncSetAttribute(k_gcnqkv, cudaFuncAttributeMaxDynamicSharedMemorySize, (int)sizeof(SG));
    cudaFuncSetAttribute(k_attnff, cudaFuncAttributeMaxDynamicSharedMemorySize, (int)sizeof(SAF));
    cudaFuncSetAttribute(k_dec,    cudaFuncAttributeMaxDynamicSharedMemorySize, (int)sizeof(SDec3));

    k_zero_counts<<<(NN + 255) / 256, 256>>>();
    k_count<<<(MM + 255) / 256, 256>>>(ei);
    k_dinv<<<(NN + 255) / 256, 256>>>();
    k_blockscan<<<NBLK, 1024>>>();
    k_scan2<<<1, 128>>>();
    k_apply<<<(NN + 255) / 256, 256>>>();
    k_fill<<<(MM + 255) / 256, 256>>>(ei);
    k_ck<<<1, 64>>>(W_proj, b_proj, u, useq);
    k_proj<<<NN / 4, 256>>>(x, W_proj);
    k_aggregate<<<NN, 192>>>();
    k_gcnqkv<<<1184, 384, sizeof(SG)>>>(W_gcn, b_gcn, Wk, bk, Wv, bv, Wq, bq);
    k_attnff<<<592, 384, sizeof(SAF)>>>(Wo, bo, ln1g, ln1b, W_ff1, b_ff1, W_ff2, b_ff2, ln2g, ln2b);
    k_predec<<<1184, 256>>>(Wd1, bd1);
    k_dec<<<2048, 256, sizeof(SDec3)>>>(ei, eattr, eseq, Wd1, Wd2, bd2, Wd3, bd3, out);
}

// round 7
// speedup vs baseline: 2.4785x; 1.0864x over previous
#include <cuda_runtime.h>
#include <cuda_fp16.h>
#include <math.h>

#define NN 100000
#define MM 800000
#define KK 6
#define HH 64
#define NHD 4
#define DHD 16
#define NBLK 98   // ceil(NN/1024)
#define WSTR 66   // padded transposed-weight row stride (floats)

typedef unsigned long long ull;

// ---------------- packed f32x2 helpers (sm_103a FFMA2 path) ----------------
__device__ __forceinline__ ull pack2(float lo, float hi) {
    ull r;
    asm("mov.b64 %0, {%1, %2};" : "=l"(r) : "f"(lo), "f"(hi));
    return r;
}
__device__ __forceinline__ void ffma2(ull& d, ull a, ull b) {
    asm("fma.rn.f32x2 %0, %1, %2, %0;" : "+l"(d) : "l"(a), "l"(b));
}
__device__ __forceinline__ float2 unpack2(ull v) {
    float lo, hi;
    asm("mov.b64 {%0, %1}, %2;" : "=f"(lo), "=f"(hi) : "l"(v));
    return make_float2(lo, hi);
}
__device__ __forceinline__ float hsum2(ull v) {
    float2 p = unpack2(v);
    return p.x + p.y;
}

// ---------------- scratch (device globals; allocation-free) ----------------
__device__ __half g_hh[NN * KK * HH];    // hs = tanh(proj)*dinv, fp16 (76.8 MB, L2-resident)
__device__ float g_h2r5[NN * HH];        // post-GCN relu, row k=5 only (residual)
__device__ float g_kv[NN * KK * 2 * HH]; // per (n,k) row: [k(64) | v(64)]
__device__ float g_q[NN * HH];           // q of row k=5
__device__ float g_pa[NN * HH];          // h_final @ Wd1[0:64]
__device__ float g_pb[NN * HH];          // h_final @ Wd1[64:128] + b1
__device__ float g_dinv[NN];
__device__ int   g_counts[NN];
__device__ int   g_scan[NN];
__device__ int   g_blocksum[128];
__device__ int   g_blockoff[128];
__device__ int   g_rowstart[NN + 1];
__device__ int   g_cursor[NN];
__device__ int   g_srclist[MM];
__device__ float g_ck[KK * HH];

// ---------------- small utility kernels ----------------
__global__ void k_zero_counts() {
    int i = blockIdx.x * blockDim.x + threadIdx.x;
    if (i < NN) g_counts[i] = 0;
}

__global__ void k_count(const int* __restrict__ ei) {
    int e = blockIdx.x * blockDim.x + threadIdx.x;
    if (e < MM) atomicAdd(&g_counts[ei[MM + e]], 1);
}

__global__ void k_dinv() {
    int n = blockIdx.x * blockDim.x + threadIdx.x;
    if (n < NN) g_dinv[n] = rsqrtf((float)g_counts[n] + 1.0f);
}

// ---------------- coalesced 3-phase scan ----------------
__global__ __launch_bounds__(1024) void k_blockscan() {
    __shared__ int warpsums[32];
    int t = threadIdx.x, lane = t & 31, w = t >> 5;
    int i = blockIdx.x * 1024 + t;
    int v0 = (i < NN) ? g_counts[i] : 0;
    int v = v0;
#pragma unroll
    for (int off = 1; off < 32; off <<= 1) {
        int x = __shfl_up_sync(0xffffffffu, v, off);
        if (lane >= off) v += x;
    }
    if (lane == 31) warpsums[w] = v;
    __syncthreads();
    if (w == 0) {
        int s = warpsums[lane];
#pragma unroll
        for (int off = 1; off < 32; off <<= 1) {
            int x = __shfl_up_sync(0xffffffffu, s, off);
            if (lane >= off) s += x;
        }
        warpsums[lane] = s;
    }
    __syncthreads();
    int incl = v + (w > 0 ? warpsums[w - 1] : 0);
    if (i < NN) g_scan[i] = incl;
    if (t == 1023) g_blocksum[blockIdx.x] = incl;
}

__global__ void k_scan2() {
    __shared__ int warpsums[4];
    int t = threadIdx.x, lane = t & 31, w = t >> 5;
    int v0 = (t < NBLK) ? g_blocksum[t] : 0;
    int v = v0;
#pragma unroll
    for (int off = 1; off < 32; off <<= 1) {
        int x = __shfl_up_sync(0xffffffffu, v, off);
        if (lane >= off) v += x;
    }
    if (lane == 31) warpsums[w] = v;
    __syncthreads();
    int base = 0;
    for (int j = 0; j < w; j++) base += warpsums[j];
    int incl = v + base;
    if (t < NBLK) g_blockoff[t] = incl - v0;
    if (t == NBLK - 1) g_rowstart[NN] = incl;
}

__global__ void k_apply() {
    int i = blockIdx.x * blockDim.x + threadIdx.x;
    if (i < NN) {
        int excl = g_scan[i] - g_counts[i] + g_blockoff[i >> 10];
        g_rowstart[i] = excl;
        g_cursor[i]   = excl;
    }
}

__global__ void k_fill(const int* __restrict__ ei) {
    int e = blockIdx.x * blockDim.x + threadIdx.x;
    if (e < MM) {
        int d = ei[MM + e];
        int p = atomicAdd(&g_cursor[d], 1);
        g_srclist[p] = ei[e];
    }
}

// c[k][c] = b_proj[c] + sum_j u[j]*Wp[12+j][c] + sum_j u_seq[k][j]*Wp[23+j][c]
__global__ void k_ck(const float* __restrict__ W_proj, const float* __restrict__ b_proj,
                     const float* __restrict__ u, const float* __restrict__ u_seq) {
    int c = threadIdx.x;
    if (c >= HH) return;
    float base = b_proj[c];
#pragma unroll
    for (int j = 0; j < 11; j++) base += u[j] * W_proj[(12 + j) * HH + c];
    for (int k = 0; k < KK; k++) {
        float val = base;
#pragma unroll
        for (int j = 0; j < 5; j++) val += u_seq[k * 5 + j] * W_proj[(23 + j) * HH + c];
        g_ck[k * HH + c] = val;
    }
}

// ---------------- projection: hs[n,k,c] = tanh(dot12 + ck) * dinv[n], fp16 ----------
__global__ __launch_bounds__(256) void k_proj(const float* __restrict__ x,
                                              const float* __restrict__ W_proj) {
    __shared__ float Wp12[12 * HH];
    __shared__ float cks[KK * HH];
    int t = threadIdx.x;
    for (int i = t; i < 12 * HH; i += 256) Wp12[i] = W_proj[i];
    for (int i = t; i < KK * HH; i += 256) cks[i] = g_ck[i];
    __syncthreads();
    int g = t >> 6, c = t & 63;
    int n = blockIdx.x * 4 + g;
    float dn = g_dinv[n];
    float s = 0.f;
#pragma unroll
    for (int j = 0; j < 12; j++) s += __ldg(&x[n * 12 + j]) * Wp12[j * HH + c];
    int base = n * (KK * HH) + c;
#pragma unroll
    for (int k = 0; k < KK; k++)
        g_hh[base + k * HH] = __float2half(tanhf(s + cks[k * HH + c]) * dn);
}

// ---------------- fused AGGREGATE + GCN + KV + Q (warp per node) ----------------
struct __align__(16) SG {
    float Wgt[HH * WSTR];       // Wgt[c*66+j] = W_gcn[j][c]
    float Wkvt[128 * WSTR];     // Wkvt[c*66+j] = [Wk|Wv][j][c]
    float Wqt[HH * WSTR];
    float arow[12][KK][HH];     // aggregated rows (j contiguous)
    float h2s[12][KK][HH];
    float bg[HH], bkv[128], bq[HH];
};

__global__ __launch_bounds__(384) void k_gcnqkv(
    const float* __restrict__ W_gcn, const float* __restrict__ b_gcn,
    const float* __restrict__ Wk, const float* __restrict__ bk,
    const float* __restrict__ Wv, const float* __restrict__ bv,
    const float* __restrict__ Wq, const float* __restrict__ bq) {
    extern __shared__ char smem_raw[];
    SG& s = *reinterpret_cast<SG*>(smem_raw);
    int t = threadIdx.x, w = t >> 5, l = t & 31;
    for (int i = t; i < HH * HH; i += 384) {
        int j = i >> 6, c = i & 63;
        s.Wgt[c * WSTR + j] = W_gcn[i];
        s.Wqt[c * WSTR + j] = Wq[i];
        s.Wkvt[c * WSTR + j] = Wk[i];
        s.Wkvt[(c + 64) * WSTR + j] = Wv[i];
    }
    if (t < HH) { s.bg[t] = b_gcn[t]; s.bq[t] = bq[t]; s.bkv[t] = bk[t]; s.bkv[64 + t] = bv[t]; }
    __syncthreads();
    const int c0 = l, c1 = l + 32;
    const __half2* hh2 = (const __half2*)g_hh;
    for (int n = blockIdx.x * 12 + w; n < NN; n += gridDim.x * 12) {
        // stage 0: aggregate neighbors: arow[r] = dn * (hs[n][r] + sum_src hs[src][r])
        {
            float dn = g_dinv[n];
            int s0 = g_rowstart[n], s1 = g_rowstart[n + 1];
            float2 acc[KK];
#pragma unroll
            for (int r = 0; r < KK; r++)
                acc[r] = __half22float2(hh2[(n * KK + r) * 32 + l]);
            int i = s0;
            for (; i + 1 < s1; i += 2) {
                int sa = g_srclist[i], sb = g_srclist[i + 1];
                const __half2* pa = hh2 + sa * (KK * 32) + l;
                const __half2* pb = hh2 + sb * (KK * 32) + l;
#pragma unroll
                for (int r = 0; r < KK; r++) {
                    float2 va = __half22float2(pa[r * 32]);
                    float2 vb = __half22float2(pb[r * 32]);
                    acc[r].x += va.x + vb.x;
                    acc[r].y += va.y + vb.y;
                }
            }
            if (i < s1) {
                const __half2* pa = hh2 + g_srclist[i] * (KK * 32) + l;
#pragma unroll
                for (int r = 0; r < KK; r++) {
                    float2 va = __half22float2(pa[r * 32]);
                    acc[r].x += va.x;
                    acc[r].y += va.y;
                }
            }
#pragma unroll
            for (int r = 0; r < KK; r++) {
                s.arow[w][r][2 * l]     = acc[r].x * dn;
                s.arow[w][r][2 * l + 1] = acc[r].y * dn;
            }
        }
        __syncwarp();
        // stage 1: h2 = relu(agg @ Wg + bg) — cols (l, l+32), 6 rows, packed j-pairs
        {
            ull acc[KK][2];
#pragma unroll
            for (int r = 0; r < KK; r++) { acc[r][0] = 0ull; acc[r][1] = 0ull; }
#pragma unroll
            for (int j2 = 0; j2 < 32; j2++) {
                ull w0 = *(const ull*)&s.Wgt[c0 * WSTR + 2 * j2];
                ull w1 = *(const ull*)&s.Wgt[c1 * WSTR + 2 * j2];
#pragma unroll
                for (int r = 0; r < KK; r++) {
                    ull av = *(const ull*)&s.arow[w][r][2 * j2];
                    ffma2(acc[r][0], av, w0);
                    ffma2(acc[r][1], av, w1);
                }
            }
#pragma unroll
            for (int r = 0; r < KK; r++) {
                float h0 = fmaxf(hsum2(acc[r][0]) + s.bg[c0], 0.f);
                float h1 = fmaxf(hsum2(acc[r][1]) + s.bg[c1], 0.f);
                s.h2s[w][r][c0] = h0;
                s.h2s[w][r][c1] = h1;
                if (r == KK - 1) {
                    g_h2r5[n * HH + c0] = h0;
                    g_h2r5[n * HH + c1] = h1;
                }
            }
        }
        __syncwarp();
        // stage 2: kv = h2 @ [Wk|Wv] + b — 4 cols/lane, 6 rows, packed j-pairs
        {
            ull acc[KK][4];
#pragma unroll
            for (int r = 0; r < KK; r++)
#pragma unroll
                for (int q = 0; q < 4; q++) acc[r][q] = 0ull;
#pragma unroll
            for (int j2 = 0; j2 < 32; j2++) {
                ull w0 = *(const ull*)&s.Wkvt[(l)      * WSTR + 2 * j2];
                ull w1 = *(const ull*)&s.Wkvt[(l + 32) * WSTR + 2 * j2];
                ull w2 = *(const ull*)&s.Wkvt[(l + 64) * WSTR + 2 * j2];
                ull w3 = *(const ull*)&s.Wkvt[(l + 96) * WSTR + 2 * j2];
#pragma unroll
                for (int r = 0; r < KK; r++) {
                    ull hv = *(const ull*)&s.h2s[w][r][2 * j2];
                    ffma2(acc[r][0], hv, w0);
                    ffma2(acc[r][1], hv, w1);
                    ffma2(acc[r][2], hv, w2);
                    ffma2(acc[r][3], hv, w3);
                }
            }
#pragma unroll
            for (int r = 0; r < KK; r++) {
                float* kvp = &g_kv[(n * KK + r) * 128];
                kvp[l]      = hsum2(acc[r][0]) + s.bkv[l];
                kvp[l + 32] = hsum2(acc[r][1]) + s.bkv[l + 32];
                kvp[l + 64] = hsum2(acc[r][2]) + s.bkv[l + 64];
                kvp[l + 96] = hsum2(acc[r][3]) + s.bkv[l + 96];
            }
        }
        // stage 3: q = h2row5 @ Wq + bq
        {
            ull a0 = 0ull, a1 = 0ull;
#pragma unroll
            for (int j2 = 0; j2 < 32; j2++) {
                ull hv = *(const ull*)&s.h2s[w][KK - 1][2 * j2];
                ull w0 = *(const ull*)&s.Wqt[c0 * WSTR + 2 * j2];
                ull w1 = *(const ull*)&s.Wqt[c1 * WSTR + 2 * j2];
                ffma2(a0, hv, w0);
                ffma2(a1, hv, w1);
            }
            g_q[n * HH + c0] = hsum2(a0) + s.bq[c0];
            g_q[n * HH + c1] = hsum2(a1) + s.bq[c1];
        }
        __syncwarp();
    }
}

// ---- fused attention tail + LN1 + FF + LN2 + decoder-precompute (warp per node) ----
struct __align__(16) SAF {
    float Wot[HH * WSTR];
    float W1t[128 * WSTR];
    float W2t[HH * 130];
    float Wat[HH * WSTR];     // Wd1 rows 0..63 transposed
    float Wbt[HH * WSTR];     // Wd1 rows 64..127 transposed
    float kv[12][KK * 128];
    float qv[12][HH];
    float ao[12][HH];
    float hm[12][HH];
    float z1[12][2 * HH];     // FF hidden; reused to share hfinal
    float aw[12][NHD * KK];
    float bo[HH], g1[HH], b1[HH], bb2[HH], g2[HH], be2[HH], b1d[HH];
    float bb1[2 * HH];
};

__global__ __launch_bounds__(384) void k_attnff(
    const float* __restrict__ Wo, const float* __restrict__ bo,
    const float* __restrict__ ln1g, const float* __restrict__ ln1b,
    const float* __restrict__ W_ff1, const float* __restrict__ b_ff1,
    const float* __restrict__ W_ff2, const float* __restrict__ b_ff2,
    const float* __restrict__ ln2g, const float* __restrict__ ln2b,
    const float* __restrict__ Wd1, const float* __restrict__ bd1) {
    extern __shared__ char smem_raw[];
    SAF& s = *reinterpret_cast<SAF*>(smem_raw);
    int t = threadIdx.x, w = t >> 5, l = t & 31;
    for (int i = t; i < HH * HH; i += 384) {
        int j = i >> 6, c = i & 63;
        s.Wot[c * WSTR + j] = Wo[i];
        s.Wat[c * WSTR + j] = Wd1[i];
        s.Wbt[c * WSTR + j] = Wd1[HH * HH + i];
    }
    for (int i = t; i < HH * 128; i += 384) {
        int j = i >> 7, c = i & 127;
        s.W1t[c * WSTR + j] = W_ff1[i];
    }
    for (int i = t; i < 128 * HH; i += 384) {
        int j = i >> 6, c = i & 63;
        s.W2t[c * 130 + j] = W_ff2[i];
    }
    if (t < HH) {
        s.bo[t] = bo[t]; s.g1[t] = ln1g[t]; s.b1[t] = ln1b[t];
        s.bb2[t] = b_ff2[t]; s.g2[t] = ln2g[t]; s.be2[t] = ln2b[t];
        s.b1d[t] = bd1[t];
    }
    if (t < 2 * HH) s.bb1[t] = b_ff1[t];
    __syncthreads();
    const int c0 = l, c1 = l + 32;
    int c2 = 2 * l, c4 = 4 * l;
    for (int n = blockIdx.x * 12 + w; n < NN; n += gridDim.x * 12) {
        // load q and kv
        s.qv[w][l]      = g_q[n * HH + l];
        s.qv[w][l + 32] = g_q[n * HH + 32 + l];
#pragma unroll
        for (int r = 0; r < KK; r++) {
            float4 v = *(const float4*)&g_kv[(n * KK + r) * 128 + c4];
            *(float4*)&s.kv[w][r * 128 + c4] = v;
        }
        __syncwarp();
        // scores
        float sc = 0.f;
        int hh = l / KK, kk = l - hh * KK;
        if (l < NHD * KK) {
#pragma unroll
            for (int d = 0; d < DHD; d++)
                sc += s.qv[w][hh * DHD + d] * s.kv[w][kk * 128 + hh * DHD + d];
            sc *= 0.25f;
        }
        float mysc[KK];
#pragma unroll
        for (int j = 0; j < KK; j++)
            mysc[j] = __shfl_sync(0xffffffffu, sc, (l & 3) * KK + j);
        if (l < NHD) {
            float mx = mysc[0];
#pragma unroll
            for (int j = 1; j < KK; j++) mx = fmaxf(mx, mysc[j]);
            float sum = 0.f;
#pragma unroll
            for (int j = 0; j < KK; j++) { mysc[j] = expf(mysc[j] - mx); sum += mysc[j]; }
            float inv = 1.0f / sum;
#pragma unroll
            for (int j = 0; j < KK; j++) s.aw[w][l * KK + j] = mysc[j] * inv;
        }
        __syncwarp();
        // AV
        int hd = l >> 3;
        float a0 = 0.f, a1 = 0.f;
#pragma unroll
        for (int j = 0; j < KK; j++) {
            float wgt = s.aw[w][hd * KK + j];
            float2 vv = *(const float2*)&s.kv[w][j * 128 + 64 + c2];
            a0 += wgt * vv.x; a1 += wgt * vv.y;
        }
        s.ao[w][c2] = a0; s.ao[w][c2 + 1] = a1;
        __syncwarp();
        // Wo GEMV + residual + LN1
        ull o0 = 0ull, o1 = 0ull;
#pragma unroll
        for (int j2 = 0; j2 < 32; j2++) {
            ull av = *(const ull*)&s.ao[w][2 * j2];
            ull w0 = *(const ull*)&s.Wot[c0 * WSTR + 2 * j2];
            ull w1 = *(const ull*)&s.Wot[c1 * WSTR + 2 * j2];
            ffma2(o0, av, w0);
            ffma2(o1, av, w1);
        }
        float y0 = g_h2r5[n * HH + c0] + hsum2(o0) + s.bo[c0];
        float y1 = g_h2r5[n * HH + c1] + hsum2(o1) + s.bo[c1];
        float s1 = y0 + y1, s2 = y0 * y0 + y1 * y1;
#pragma unroll
        for (int off = 16; off > 0; off >>= 1) {
            s1 += __shfl_xor_sync(0xffffffffu, s1, off);
            s2 += __shfl_xor_sync(0xffffffffu, s2, off);
        }
        float m = s1 * (1.0f / HH);
        float var = s2 * (1.0f / HH) - m * m;
        float rstd = rsqrtf(var + 1e-5f);
        float hm0 = (y0 - m) * rstd * s.g1[c0] + s.b1[c0];
        float hm1 = (y1 - m) * rstd * s.g1[c1] + s.b1[c1];
        s.hm[w][c0] = hm0; s.hm[w][c1] = hm1;
        __syncwarp();
        // FF1: z1 = relu(hm @ W1 + b1)
        {
            ull f0 = 0ull, f1 = 0ull, f2 = 0ull, f3 = 0ull;
#pragma unroll
            for (int j2 = 0; j2 < 32; j2++) {
                ull hv = *(const ull*)&s.hm[w][2 * j2];
                ull w0 = *(const ull*)&s.W1t[(l)      * WSTR + 2 * j2];
                ull w1 = *(const ull*)&s.W1t[(l + 32) * WSTR + 2 * j2];
                ull w2 = *(const ull*)&s.W1t[(l + 64) * WSTR + 2 * j2];
                ull w3 = *(const ull*)&s.W1t[(l + 96) * WSTR + 2 * j2];
                ffma2(f0, hv, w0);
                ffma2(f1, hv, w1);
                ffma2(f2, hv, w2);
                ffma2(f3, hv, w3);
            }
            s.z1[w][l]      = fmaxf(hsum2(f0) + s.bb1[l], 0.f);
            s.z1[w][l + 32] = fmaxf(hsum2(f1) + s.bb1[l + 32], 0.f);
            s.z1[w][l + 64] = fmaxf(hsum2(f2) + s.bb1[l + 64], 0.f);
            s.z1[w][l + 96] = fmaxf(hsum2(f3) + s.bb1[l + 96], 0.f);
        }
        __syncwarp();
        // FF2 + residual + LN2 -> hfinal (registers)
        ull g0 = 0ull, g1a = 0ull;
#pragma unroll
        for (int j2 = 0; j2 < 64; j2++) {
            ull zv = *(const ull*)&s.z1[w][2 * j2];
            ull w0 = *(const ull*)&s.W2t[c0 * 130 + 2 * j2];
            ull w1 = *(const ull*)&s.W2t[c1 * 130 + 2 * j2];
            ffma2(g0, zv, w0);
            ffma2(g1a, zv, w1);
        }
        float u0 = hm0 + hsum2(g0) + s.bb2[c0];
        float u1 = hm1 + hsum2(g1a) + s.bb2[c1];
        float t1 = u0 + u1, t2 = u0 * u0 + u1 * u1;
#pragma unroll
        for (int off = 16; off > 0; off >>= 1) {
            t1 += __shfl_xor_sync(0xffffffffu, t1, off);
            t2 += __shfl_xor_sync(0xffffffffu, t2, off);
        }
        float m2 = t1 * (1.0f / HH);
        float var2 = t2 * (1.0f / HH) - m2 * m2;
        float rstd2 = rsqrtf(var2 + 1e-5f);
        float hf0 = (u0 - m2) * rstd2 * s.g2[c0] + s.be2[c0];
        float hf1 = (u1 - m2) * rstd2 * s.g2[c1] + s.be2[c1];
        __syncwarp();
        // decoder precompute: pa = hf@W1a, pb = hf@W1b + b1 (share hf via z1 buffer)
        s.z1[w][c0] = hf0; s.z1[w][c1] = hf1;
        __syncwarp();
        ull pa0 = 0ull, pa1 = 0ull, pb0 = 0ull, pb1 = 0ull;
#pragma unroll
        for (int j2 = 0; j2 < 32; j2++) {
            ull v = *(const ull*)&s.z1[w][2 * j2];
            ull wa0 = *(const ull*)&s.Wat[c0 * WSTR + 2 * j2];
            ull wa1 = *(const ull*)&s.Wat[c1 * WSTR + 2 * j2];
            ull wb0 = *(const ull*)&s.Wbt[c0 * WSTR + 2 * j2];
            ull wb1 = *(const ull*)&s.Wbt[c1 * WSTR + 2 * j2];
            ffma2(pa0, v, wa0);
            ffma2(pa1, v, wa1);
            ffma2(pb0, v, wb0);
            ffma2(pb1, v, wb1);
        }
        g_pa[n * HH + c0] = hsum2(pa0);
        g_pa[n * HH + c1] = hsum2(pa1);
        g_pb[n * HH + c0] = hsum2(pb0) + s.b1d[c0];
        g_pb[n * HH + c1] = hsum2(pb1) + s.b1d[c1];
        __syncwarp();
    }
}

// ---------------- edge decoder (factorized, FFMA2 W2) ----------------
struct __align__(16) SDec3 {
    float z1[8][HH];      // offset 0 (8B-aligned) — required for LDS.64
    float2 W2p[32][32];
    float W1c[5 * HH];
    float W1d[4 * HH];
    float W3[32];
    float b2[32];
    float b3;
};

__global__ __launch_bounds__(256) void k_dec(
    const int* __restrict__ ei,
    const float* __restrict__ edge_attr, const float* __restrict__ edge_seq,
    const float* __restrict__ Wd1,
    const float* __restrict__ Wd2, const float* __restrict__ bd2,
    const float* __restrict__ Wd3, const float* __restrict__ bd3,
    float* __restrict__ out) {
    extern __shared__ char smem_raw[];
    SDec3& s = *reinterpret_cast<SDec3*>(smem_raw);
    int t = threadIdx.x, w = t >> 5, l = t & 31;
    for (int i = t; i < 5 * HH; i += 256) s.W1c[i] = Wd1[(2 * HH) * HH + i];
    for (int i = t; i < 4 * HH; i += 256) s.W1d[i] = Wd1[(2 * HH + 5) * HH + i];
    for (int i = t; i < 1024; i += 256) {
        int j = i >> 5, ll = i & 31;
        s.W2p[j][ll] = make_float2(Wd2[(2 * j) * 32 + ll], Wd2[(2 * j + 1) * 32 + ll]);
    }
    if (t < 32) { s.W3[t] = Wd3[t]; s.b2[t] = bd2[t]; }
    if (t == 0) s.b3 = bd3[0];
    __syncthreads();
    float* z1 = s.z1[w];
    int c = 2 * l;
    for (int e = blockIdx.x * 8 + w; e < MM; e += gridDim.x * 8) {
        int src = ei[e], dst = ei[MM + e];
        float2 pav = *(const float2*)&g_pa[src * HH + c];
        float2 pbv = *(const float2*)&g_pb[dst * HH + c];
        float zx = pav.x + pbv.x, zy = pav.y + pbv.y;
#pragma unroll
        for (int j = 0; j < 5; j++) {
            float ev = __ldg(&edge_attr[e * 5 + j]);
            float2 wv = *(const float2*)&s.W1c[j * HH + c];
            zx += ev * wv.x; zy += ev * wv.y;
        }
#pragma unroll
        for (int j = 0; j < 4; j++) {
            float ev = __ldg(&edge_seq[e * (KK * 4) + (KK - 1) * 4 + j]);
            float2 wv = *(const float2*)&s.W1d[j * HH + c];
            zx += ev * wv.x; zy += ev * wv.y;
        }
        z1[c] = fmaxf(zx, 0.f);
        z1[c + 1] = fmaxf(zy, 0.f);
        __syncwarp();
        ull acc = pack2(s.b2[l], 0.f);
#pragma unroll
        for (int j = 0; j < 32; j++) {
            ull z2 = *(const ull*)&z1[2 * j];
            ull w2 = *(const ull*)&s.W2p[j][l];
            ffma2(acc, z2, w2);
        }
        float2 av = unpack2(acc);
        float a2 = fmaxf(av.x + av.y, 0.f);
        float p = a2 * s.W3[l];
#pragma unroll
        for (int off = 16; off > 0; off >>= 1) p += __shfl_down_sync(0xffffffffu, p, off);
        if (l == 0) out[e] = p + s.b3;
        __syncwarp();
    }
}

// ---------------- launch ----------------
extern "C" void kernel_launch(void* const* d_in, const int* in_sizes, int n_in,
                              void* d_out, int out_size) {
    const float* x        = (const float*)d_in[0];
    const int*   ei       = (const int*)  d_in[1];
    const float* eattr    = (const float*)d_in[2];
    const float* u        = (const float*)d_in[3];
    const float* eseq     = (const float*)d_in[4];
    const float* useq     = (const float*)d_in[5];
    const float* W_proj   = (const float*)d_in[6];
    const float* b_proj   = (const float*)d_in[7];
    const float* W_gcn    = (const float*)d_in[8];
    const float* b_gcn    = (const float*)d_in[9];
    const float* Wq       = (const float*)d_in[10];
    const float* bq       = (const float*)d_in[11];
    const float* Wk       = (const float*)d_in[12];
    const float* bk       = (const float*)d_in[13];
    const float* Wv       = (const float*)d_in[14];
    const float* bv       = (const float*)d_in[15];
    const float* Wo       = (const float*)d_in[16];
    const float* bo       = (const float*)d_in[17];
    const float* ln1g     = (const float*)d_in[18];
    const float* ln1b     = (const float*)d_in[19];
    const float* W_ff1    = (const float*)d_in[20];
    const float* b_ff1    = (const float*)d_in[21];
    const float* W_ff2    = (const float*)d_in[22];
    const float* b_ff2    = (const float*)d_in[23];
    const float* ln2g     = (const float*)d_in[24];
    const float* ln2b     = (const float*)d_in[25];
    const float* Wd1      = (const float*)d_in[26];
    const float* bd1      = (const float*)d_in[27];
    const float* Wd2      = (const float*)d_in[28];
    const float* bd2      = (const float*)d_in[29];
    const float* Wd3      = (const float*)d_in[30];
    const float* bd3      = (const float*)d_in[31];
    float* out = (float*)d_out;

    cudaFuncSetAttribute(k_gcnqkv, cudaFuncAttributeMaxDynamicSharedMemorySize, (int)sizeof(SG));
    cudaFuncSetAttribute(k_attnff, cudaFuncAttributeMaxDynamicSharedMemorySize, (int)sizeof(SAF));
    cudaFuncSetAttribute(k_dec,    cudaFuncAttributeMaxDynamicSharedMemorySize, (int)sizeof(SDec3));

    k_zero_counts<<<(NN + 255) / 256, 256>>>();
    k_count<<<(MM + 255) / 256, 256>>>(ei);
    k_dinv<<<(NN + 255) / 256, 256>>>();
    k_blockscan<<<NBLK, 1024>>>();
    k_scan2<<<1, 128>>>();
    k_apply<<<(NN + 255) / 256, 256>>>();
    k_fill<<<(MM + 255) / 256, 256>>>(ei);
    k_ck<<<1, 64>>>(W_proj, b_proj, u, useq);
    k_proj<<<NN / 4, 256>>>(x, W_proj);
    k_gcnqkv<<<1184, 384, sizeof(SG)>>>(W_gcn, b_gcn, Wk, bk, Wv, bv, Wq, bq);
    k_attnff<<<592, 384, sizeof(SAF)>>>(Wo, bo, ln1g, ln1b, W_ff1, b_ff1,
                                        W_ff2, b_ff2, ln2g, ln2b, Wd1, bd1);
    k_dec<<<2048, 256, sizeof(SDec3)>>>(ei, eattr, eseq, Wd1, Wd2, bd2, Wd3, bd3, out);
}